// round 6
// baseline (speedup 1.0000x reference)
#include <cuda_runtime.h>
#include <cuda_bf16.h>
#include <math.h>
#include <stdint.h>

// ---------------- problem constants ----------------
#define MAXN 50000
#define MAXE 800000
#define MAXNE 100000
#define D 128

// ---------------- device scratch ----------------
// A operands pre-split to bf16 hi/lo (padded +128 rows so cp.async tails stay in-bounds)
__device__ __nv_bfloat16 g_Ahi[(size_t)(MAXNE + 128) * D];
__device__ __nv_bfloat16 g_Alo[(size_t)(MAXNE + 128) * D];
__device__ float g_Hf [(size_t)MAXN * D];     // GEMM trunk output (pre-agg)
__device__ float g_emb[(size_t)MAXN * D];     // final embeddings (fp32 for products)
__device__ int   g_deg[MAXN];
__device__ int   g_rowptr[MAXN + 1];
__device__ int   g_cur[MAXN];
__device__ int   g_eidx[MAXE];
__device__ int   g_bsum[256];
// pre-transposed bf16 weights Wt[n][k] (5 x 128x128), hi & lo halves
__device__ __nv_bfloat16 g_Whi[5 * 16384];
__device__ __nv_bfloat16 g_Wlo[5 * 16384];

// ---------------- PTX helpers ----------------
__device__ __forceinline__ uint32_t smem_u32(const void* p) {
    uint32_t a;
    asm("{ .reg .u64 t; cvta.to.shared.u64 t, %1; cvt.u32.u64 %0, t; }" : "=r"(a) : "l"(p));
    return a;
}
__device__ __forceinline__ void ldsm4(uint32_t* r, uint32_t addr) {
    asm volatile("ldmatrix.sync.aligned.m8n8.x4.shared.b16 {%0,%1,%2,%3}, [%4];"
        : "=r"(r[0]), "=r"(r[1]), "=r"(r[2]), "=r"(r[3]) : "r"(addr));
}
__device__ __forceinline__ void mma16816(float* c, const uint32_t* a, const uint32_t* b) {
    asm volatile(
        "mma.sync.aligned.m16n8k16.row.col.f32.bf16.bf16.f32 "
        "{%0,%1,%2,%3}, {%4,%5,%6,%7}, {%8,%9}, {%0,%1,%2,%3};"
        : "+f"(c[0]), "+f"(c[1]), "+f"(c[2]), "+f"(c[3])
        : "r"(a[0]), "r"(a[1]), "r"(a[2]), "r"(a[3]), "r"(b[0]), "r"(b[1]));
}
__device__ __forceinline__ void cp_async16(uint32_t saddr, const void* gptr) {
    asm volatile("cp.async.cg.shared.global [%0], [%1], 16;" :: "r"(saddr), "l"(gptr));
}
#define CP_COMMIT() asm volatile("cp.async.commit_group;" ::: "memory")
template <int NN> __device__ __forceinline__ void cp_wait() {
    asm volatile("cp.async.wait_group %0;" :: "n"(NN) : "memory");
}

// split helper: fp32 -> (hi, lo) bf16
__device__ __forceinline__ void split2(float a, float b, uint32_t& hi, uint32_t& lo) {
    __nv_bfloat162 h = __floats2bfloat162_rn(a, b);
    float ra = a - __bfloat162float(h.x);
    float rb = b - __bfloat162float(h.y);
    __nv_bfloat162 l = __floats2bfloat162_rn(ra, rb);
    hi = *(uint32_t*)&h;
    lo = *(uint32_t*)&l;
}

// ---------------- CSR build kernels ----------------
__global__ void zero_int_kernel(int* p, int n) {
    for (int i = blockIdx.x * blockDim.x + threadIdx.x; i < n; i += gridDim.x * blockDim.x)
        p[i] = 0;
}
__global__ void hist_kernel(const int* __restrict__ dst, int E, int* __restrict__ deg) {
    for (int e = blockIdx.x * blockDim.x + threadIdx.x; e < E; e += gridDim.x * blockDim.x)
        atomicAdd(&deg[dst[e]], 1);
}
__global__ void scan1_kernel(const int* __restrict__ deg, int* __restrict__ rowptr,
                             int* __restrict__ bsum, int n) {
    __shared__ int wsum[32];
    int tid = threadIdx.x, lane = tid & 31, w = tid >> 5;
    int i = blockIdx.x * 1024 + tid;
    int v = (i < n) ? deg[i] : 0;
    int s = v;
    #pragma unroll
    for (int off = 1; off < 32; off <<= 1) {
        int t = __shfl_up_sync(0xFFFFFFFFu, s, off);
        if (lane >= off) s += t;
    }
    if (lane == 31) wsum[w] = s;
    __syncthreads();
    if (w == 0) {
        int ws = wsum[lane];
        #pragma unroll
        for (int off = 1; off < 32; off <<= 1) {
            int t = __shfl_up_sync(0xFFFFFFFFu, ws, off);
            if (lane >= off) ws += t;
        }
        wsum[lane] = ws;
    }
    __syncthreads();
    int prev = (w > 0) ? wsum[w - 1] : 0;
    int incl = prev + s;
    if (i < n) rowptr[i] = incl - v;
    if (tid == 1023) bsum[blockIdx.x] = incl;
}
__global__ void scan2_kernel(int* bsum, int nb) {
    int lane = threadIdx.x;
    int carry = 0;
    for (int base = 0; base < nb; base += 32) {
        int i = base + lane;
        int v = (i < nb) ? bsum[i] : 0;
        int s = v;
        #pragma unroll
        for (int off = 1; off < 32; off <<= 1) {
            int t = __shfl_up_sync(0xFFFFFFFFu, s, off);
            if (lane >= off) s += t;
        }
        if (i < nb) bsum[i] = carry + s - v;
        carry += __shfl_sync(0xFFFFFFFFu, s, 31);
    }
}
__global__ void scan3_kernel(const int* __restrict__ deg, int* __restrict__ rowptr,
                             int* __restrict__ cur, const int* __restrict__ bsum, int n) {
    int i = blockIdx.x * 1024 + threadIdx.x;
    if (i >= n) return;
    int val = rowptr[i] + bsum[blockIdx.x];
    rowptr[i] = val;
    cur[i] = val;
    if (i == n - 1) rowptr[n] = val + deg[n - 1];
}
__global__ void fill_csr_kernel(const int* __restrict__ src, const int* __restrict__ dst,
                                int E, int* __restrict__ cur, int* __restrict__ eidx) {
    for (int e = blockIdx.x * blockDim.x + threadIdx.x; e < E; e += gridDim.x * blockDim.x) {
        int d = dst[e];
        int p = atomicAdd(&cur[d], 1);
        eidx[p] = src[e];
    }
}

// ---------------- prep: W[k][n] fp32 -> Wt[n][k] bf16 hi/lo ----------------
__global__ void prep_weights_kernel(const float* W1, const float* W2, const float* W3,
                                    const float* P1, const float* P2,
                                    __nv_bfloat16* hi, __nv_bfloat16* lo) {
    int idx = blockIdx.x * blockDim.x + threadIdx.x;
    if (idx >= 5 * 16384) return;
    int w = idx >> 14;
    int t = idx & 16383;
    int n = t >> 7;
    int k = t & 127;
    const float* Ws = (w == 0) ? W1 : (w == 1) ? W2 : (w == 2) ? W3 : (w == 3) ? P1 : P2;
    float v = Ws[(k << 7) | n];
    __nv_bfloat16 h = __float2bfloat16(v);
    float rem = v - __bfloat162float(h);
    hi[idx] = h;
    lo[idx] = __float2bfloat16(rem);
}

// ---------------- prep: x fp32 -> Ahi/Alo ----------------
__global__ void xsplit_kernel(const float* __restrict__ x,
                              __nv_bfloat16* __restrict__ Ahi, __nv_bfloat16* __restrict__ Alo,
                              int N) {
    int n4 = N * 32;
    for (int idx = blockIdx.x * blockDim.x + threadIdx.x; idx < n4; idx += gridDim.x * blockDim.x) {
        float4 v = ((const float4*)x)[idx];
        uint2 hp, lp;
        split2(v.x, v.y, hp.x, lp.x);
        split2(v.z, v.w, hp.y, lp.y);
        *(uint2*)(Ahi + (size_t)idx * 4) = hp;
        *(uint2*)(Alo + (size_t)idx * 4) = lp;
    }
}

// ---------------- mma.sync GEMM, cp.async double-buffered ----------------
#define ASTRIDE 136
#define ABUF (128 * ASTRIDE)              // 17408 elems per A array
#define S_A0HI 0
#define S_A0LO ABUF
#define S_A1HI (2 * ABUF)
#define S_A1LO (3 * ABUF)
#define S_WHI  (4 * ABUF)
#define S_WLO  (4 * ABUF + 16384)
#define SMEM_ELEMS (4 * ABUF + 2 * 16384) // A dbl-buf + W (W unpadded? no, padded:)
// W needs ASTRIDE padding for conflict-free ldsm -> W tiles are 128*ASTRIDE too
#undef S_WLO
#undef SMEM_ELEMS
#define S_WLO  (5 * ABUF)
#define SMEM_ELEMS (6 * ABUF)             // 104448 bf16 = 208896 B
#define SMEM_BYTES (SMEM_ELEMS * 2 + (256 + 256 + 8) * 4)

// stagemode: 0 = cp.async from Ahi/Alo; 1 = ALU gather products (embf, tedg)
// epimode:   0 = fp32 C (+bias/relu); 1 = bf16 hi/lo out (+bias/relu); 2 = fused final
__global__ void __launch_bounds__(256, 1)
gemm_mma_kernel(const __nv_bfloat16* __restrict__ Ahi, const __nv_bfloat16* __restrict__ Alo,
                const float* __restrict__ embf, const int* __restrict__ tedg,
                const __nv_bfloat16* __restrict__ Wt_hi, const __nv_bfloat16* __restrict__ Wt_lo,
                const float* __restrict__ bias, float* __restrict__ Cf,
                __nv_bfloat16* __restrict__ OutHi, __nv_bfloat16* __restrict__ OutLo,
                const float* __restrict__ P3, const float* __restrict__ pb3,
                float* __restrict__ outF,
                int M, int relu, int numTiles, int stagemode, int epimode) {
    extern __shared__ __nv_bfloat16 sm[];
    uint32_t sbase = smem_u32(sm);
    float* fpart = (float*)(sm + SMEM_ELEMS);
    float* fP3 = fpart + 256;
    float* fpb3 = fP3 + 256;
    int tid = threadIdx.x, wid = tid >> 5, lane = tid & 31;

    // ---- stage Wt hi/lo (once per CTA, padded rows) ----
    {
        const uint4* wh = (const uint4*)Wt_hi;
        const uint4* wl = (const uint4*)Wt_lo;
        for (int i = tid; i < 2048; i += 256) {
            int r = i >> 4, c = i & 15;
            *(uint4*)(sm + S_WHI + r * ASTRIDE + c * 8) = wh[i];
            *(uint4*)(sm + S_WLO + r * ASTRIDE + c * 8) = wl[i];
        }
        if (epimode == 2) {
            fP3[tid] = P3[tid];
            if (tid < 2) fpb3[tid] = pb3[tid];
        }
    }

    int mrow0 = (wid >> 1) << 5;
    int ncol0 = (wid & 1) << 6;

    uint32_t aRel = (uint32_t)(mrow0 + (lane & 15)) * (ASTRIDE * 2)
                  + (uint32_t)(((lane >> 4) << 3) * 2);
    uint32_t bN = (uint32_t)(ncol0 + ((lane >> 4) << 3) + (lane & 7));
    uint32_t bKB = (uint32_t)((((lane >> 3) & 1) << 3) * 2);
    uint32_t bHiBase = sbase + (S_WHI * 2) + bN * (ASTRIDE * 2) + bKB;
    uint32_t bLoBase = bHiBase + (S_WLO - S_WHI) * 2;

    // ---- staging helper (inlined twice via lambda) ----
    auto stage = [&](int tile, int buf) {
        int row0 = tile << 7;
        uint32_t baseHi = (buf ? S_A1HI : S_A0HI);
        uint32_t baseLo = (buf ? S_A1LO : S_A0LO);
        if (stagemode == 0) {
            #pragma unroll
            for (int it = 0; it < 8; it++) {
                int idx = it * 256 + tid;          // 0..2047
                int r = idx >> 4, c = idx & 15;
                size_t goff = (size_t)(row0 + r) * D + c * 8;
                uint32_t soff = (r * ASTRIDE + c * 8) * 2;
                cp_async16(sbase + baseHi * 2 + soff, Ahi + goff);
                cp_async16(sbase + baseLo * 2 + soff, Alo + goff);
            }
            CP_COMMIT();
        } else {
            #pragma unroll
            for (int it = 0; it < 16; it++) {
                int idx = it * 256 + tid;
                int r = idx >> 5;
                int c4 = idx & 31;
                int grow = row0 + r;
                float4 v;
                if (grow < M) {
                    int s = tedg[2 * grow];
                    int d = tedg[2 * grow + 1];
                    float4 a = *(const float4*)(embf + (size_t)s * D + c4 * 4);
                    float4 b = *(const float4*)(embf + (size_t)d * D + c4 * 4);
                    v = make_float4(a.x * b.x, a.y * b.y, a.z * b.z, a.w * b.w);
                } else {
                    v = make_float4(0.f, 0.f, 0.f, 0.f);
                }
                uint2 hp, lp;
                split2(v.x, v.y, hp.x, lp.x);
                split2(v.z, v.w, hp.y, lp.y);
                *(uint2*)(sm + baseHi + r * ASTRIDE + c4 * 4) = hp;
                *(uint2*)(sm + baseLo + r * ASTRIDE + c4 * 4) = lp;
            }
        }
    };

    int t = blockIdx.x;
    if (t < numTiles) stage(t, 0);
    int parity = 0;
    for (; t < numTiles; t += gridDim.x, parity ^= 1) {
        int nxt = t + gridDim.x;
        if (nxt < numTiles) stage(nxt, parity ^ 1);
        if (stagemode == 0) {
            if (nxt < numTiles) cp_wait<1>(); else cp_wait<0>();
        }
        __syncthreads();

        int row0 = t << 7;
        uint32_t abase2 = (parity ? S_A1HI : S_A0HI) * 2;
        uint32_t aHi0 = sbase + abase2 + aRel;
        uint32_t aHi1 = aHi0 + 16 * (ASTRIDE * 2);
        uint32_t aLo0 = aHi0 + ABUF * 2;
        uint32_t aLo1 = aHi1 + ABUF * 2;

        float acc[2][8][4];
        #pragma unroll
        for (int mt = 0; mt < 2; mt++)
            #pragma unroll
            for (int nt = 0; nt < 8; nt++)
                #pragma unroll
                for (int q = 0; q < 4; q++) acc[mt][nt][q] = 0.0f;

        #pragma unroll
        for (int ks = 0; ks < 8; ks++) {
            uint32_t koffB = (uint32_t)(ks * 32);
            uint32_t ah[2][4], al[2][4];
            ldsm4(ah[0], aHi0 + koffB);
            ldsm4(ah[1], aHi1 + koffB);
            ldsm4(al[0], aLo0 + koffB);
            ldsm4(al[1], aLo1 + koffB);
            uint32_t bh[8][2], bl[8][2];
            #pragma unroll
            for (int np = 0; np < 4; np++) {
                uint32_t r4[4];
                ldsm4(r4, bHiBase + (uint32_t)(np * 16 * ASTRIDE * 2) + koffB);
                bh[2 * np][0] = r4[0]; bh[2 * np][1] = r4[1];
                bh[2 * np + 1][0] = r4[2]; bh[2 * np + 1][1] = r4[3];
                ldsm4(r4, bLoBase + (uint32_t)(np * 16 * ASTRIDE * 2) + koffB);
                bl[2 * np][0] = r4[0]; bl[2 * np][1] = r4[1];
                bl[2 * np + 1][0] = r4[2]; bl[2 * np + 1][1] = r4[3];
            }
            #pragma unroll
            for (int mt = 0; mt < 2; mt++)
                #pragma unroll
                for (int nt = 0; nt < 8; nt++) {
                    mma16816(acc[mt][nt], ah[mt], bh[nt]);
                    mma16816(acc[mt][nt], ah[mt], bl[nt]);
                    mma16816(acc[mt][nt], al[mt], bh[nt]);
                }
        }

        int cbase = ncol0 + ((lane & 3) << 1);

        if (epimode == 2) {
            float q0s[4], q1s[4];
            #pragma unroll
            for (int mt = 0; mt < 2; mt++) {
                #pragma unroll
                for (int half = 0; half < 2; half++) {
                    float q0 = 0.f, q1 = 0.f;
                    #pragma unroll
                    for (int nt = 0; nt < 8; nt++) {
                        int col = cbase + nt * 8;
                        float z0 = fmaxf(acc[mt][nt][2 * half] + bias[col], 0.f);
                        float z1 = fmaxf(acc[mt][nt][2 * half + 1] + bias[col + 1], 0.f);
                        q0 += z0 * fP3[2 * col] + z1 * fP3[2 * (col + 1)];
                        q1 += z0 * fP3[2 * col + 1] + z1 * fP3[2 * (col + 1) + 1];
                    }
                    q0 += __shfl_xor_sync(0xFFFFFFFFu, q0, 1);
                    q0 += __shfl_xor_sync(0xFFFFFFFFu, q0, 2);
                    q1 += __shfl_xor_sync(0xFFFFFFFFu, q1, 1);
                    q1 += __shfl_xor_sync(0xFFFFFFFFu, q1, 2);
                    q0s[mt * 2 + half] = q0;
                    q1s[mt * 2 + half] = q1;
                    if (ncol0 == 0 && (lane & 3) == 0) {
                        int rl = mrow0 + mt * 16 + half * 8 + (lane >> 2);
                        fpart[2 * rl] = q0;
                        fpart[2 * rl + 1] = q1;
                    }
                }
            }
            __syncthreads();
            if (ncol0 == 64 && (lane & 3) == 0) {
                #pragma unroll
                for (int mt = 0; mt < 2; mt++) {
                    #pragma unroll
                    for (int half = 0; half < 2; half++) {
                        int rl = mrow0 + mt * 16 + half * 8 + (lane >> 2);
                        int gr = row0 + rl;
                        if (gr < M) {
                            float z0 = q0s[mt * 2 + half] + fpart[2 * rl] + fpb3[0];
                            float z1 = q1s[mt * 2 + half] + fpart[2 * rl + 1] + fpb3[1];
                            float nrm = fmaxf(sqrtf(z0 * z0 + z1 * z1), 1e-12f);
                            z0 /= nrm; z1 /= nrm;
                            float mm = fmaxf(z0, z1);
                            float lse = mm + logf(expf(z0 - mm) + expf(z1 - mm));
                            outF[2 * gr]     = z0 - lse;
                            outF[2 * gr + 1] = z1 - lse;
                        }
                    }
                }
            }
        } else if (epimode == 1) {
            int rbase = row0 + mrow0 + (lane >> 2);
            #pragma unroll
            for (int mt = 0; mt < 2; mt++) {
                #pragma unroll
                for (int half = 0; half < 2; half++) {
                    int gr = rbase + mt * 16 + half * 8;
                    if (gr >= M) continue;
                    #pragma unroll
                    for (int nt = 0; nt < 8; nt++) {
                        int col = cbase + nt * 8;
                        float o0 = fmaxf(acc[mt][nt][2 * half] + bias[col], 0.f);
                        float o1 = fmaxf(acc[mt][nt][2 * half + 1] + bias[col + 1], 0.f);
                        uint32_t hp, lp;
                        split2(o0, o1, hp, lp);
                        *(uint32_t*)(OutHi + (size_t)gr * D + col) = hp;
                        *(uint32_t*)(OutLo + (size_t)gr * D + col) = lp;
                    }
                }
            }
        } else {
            int rbase = row0 + mrow0 + (lane >> 2);
            #pragma unroll
            for (int mt = 0; mt < 2; mt++) {
                #pragma unroll
                for (int half = 0; half < 2; half++) {
                    int gr = rbase + mt * 16 + half * 8;
                    if (gr >= M) continue;
                    float* cp = Cf + (size_t)gr * D;
                    #pragma unroll
                    for (int nt = 0; nt < 8; nt++) {
                        int col = cbase + nt * 8;
                        float o0 = acc[mt][nt][2 * half];
                        float o1 = acc[mt][nt][2 * half + 1];
                        if (bias) { o0 += bias[col]; o1 += bias[col + 1]; }
                        if (relu) { o0 = fmaxf(o0, 0.f); o1 = fmaxf(o1, 0.f); }
                        *(float2*)(cp + col) = make_float2(o0, o1);
                    }
                }
            }
        }
        __syncthreads();   // all reads of buf[parity] done before it is restaged
    }
}

// ---------------- aggregation: warp-per-dst; outmode 0 = bf16 hi/lo, 1 = fp32 ----
__global__ void agg_kernel(const float* __restrict__ H, const int* __restrict__ rowptr,
                           const int* __restrict__ eidx, const float* __restrict__ bias,
                           __nv_bfloat16* __restrict__ OutHi, __nv_bfloat16* __restrict__ OutLo,
                           float* __restrict__ OutF,
                           int relu, int outmode, int N) {
    int gw = (blockIdx.x * blockDim.x + threadIdx.x) >> 5;
    int lane = threadIdx.x & 31;
    if (gw >= N) return;
    int beg = rowptr[gw], end = rowptr[gw + 1];
    float4 acc = make_float4(0.f, 0.f, 0.f, 0.f);
    for (int j0 = beg; j0 < end; j0 += 32) {
        int cnt = min(32, end - j0);
        int e = (lane < cnt) ? eidx[j0 + lane] : 0;
        for (int t = 0; t < cnt; t++) {
            int s = __shfl_sync(0xFFFFFFFFu, e, t);
            float4 v = *(const float4*)(H + (size_t)s * D + (lane << 2));
            acc.x += v.x; acc.y += v.y; acc.z += v.z; acc.w += v.w;
        }
    }
    float4 bv = *(const float4*)(bias + (lane << 2));
    acc.x += bv.x; acc.y += bv.y; acc.z += bv.z; acc.w += bv.w;
    if (relu) {
        acc.x = fmaxf(acc.x, 0.f); acc.y = fmaxf(acc.y, 0.f);
        acc.z = fmaxf(acc.z, 0.f); acc.w = fmaxf(acc.w, 0.f);
    }
    if (outmode == 0) {
        uint2 hp, lp;
        split2(acc.x, acc.y, hp.x, lp.x);
        split2(acc.z, acc.w, hp.y, lp.y);
        *(uint2*)(OutHi + (size_t)gw * D + (lane << 2)) = hp;
        *(uint2*)(OutLo + (size_t)gw * D + (lane << 2)) = lp;
    } else {
        *(float4*)(OutF + (size_t)gw * D + (lane << 2)) = acc;
    }
}

// ---------------- launch ----------------
extern "C" void kernel_launch(void* const* d_in, const int* in_sizes, int n_in,
                              void* d_out, int out_size) {
    const float* x    = (const float*)d_in[0];
    const int*   adj  = (const int*)d_in[1];
    const int*   tedg = (const int*)d_in[2];
    const float* W1 = (const float*)d_in[3];  const float* b1  = (const float*)d_in[4];
    const float* W2 = (const float*)d_in[5];  const float* b2  = (const float*)d_in[6];
    const float* W3 = (const float*)d_in[7];  const float* b3  = (const float*)d_in[8];
    const float* P1 = (const float*)d_in[9];  const float* pb1 = (const float*)d_in[10];
    const float* P2 = (const float*)d_in[11]; const float* pb2 = (const float*)d_in[12];
    const float* P3 = (const float*)d_in[13]; const float* pb3 = (const float*)d_in[14];
    float* out = (float*)d_out;

    int N  = in_sizes[0] / D;
    int E  = in_sizes[1] / 2;
    int NE = in_sizes[2] / 2;

    cudaFuncSetAttribute((const void*)gemm_mma_kernel,
                         cudaFuncAttributeMaxDynamicSharedMemorySize, SMEM_BYTES);

    __nv_bfloat16 *Ahi, *Alo, *Whi, *Wlo;
    float *Hf, *emb;
    int *deg, *rowptr, *cur, *eidx, *bsum;
    cudaGetSymbolAddress((void**)&Ahi, g_Ahi);
    cudaGetSymbolAddress((void**)&Alo, g_Alo);
    cudaGetSymbolAddress((void**)&Hf,  g_Hf);
    cudaGetSymbolAddress((void**)&emb, g_emb);
    cudaGetSymbolAddress((void**)&deg,    g_deg);
    cudaGetSymbolAddress((void**)&rowptr, g_rowptr);
    cudaGetSymbolAddress((void**)&cur,    g_cur);
    cudaGetSymbolAddress((void**)&eidx,   g_eidx);
    cudaGetSymbolAddress((void**)&bsum,   g_bsum);
    cudaGetSymbolAddress((void**)&Whi,  g_Whi);
    cudaGetSymbolAddress((void**)&Wlo,  g_Wlo);

    const int* src = adj;
    const int* dst = adj + E;

    int nScanBlk = (N + 1023) / 1024;
    int tilesN  = (N + 127) / 128;
    int tilesNE = (NE + 127) / 128;
    int gN  = tilesN  < 148 ? tilesN  : 148;
    int gNE = tilesNE < 148 ? tilesNE : 148;
    int aggBlk = (N * 32 + 255) / 256;

    // ---- prep + L1 GEMM early (capture slot = GEMM), CSR chain after ----
    prep_weights_kernel<<<(5 * 16384 + 255) / 256, 256>>>(W1, W2, W3, P1, P2, Whi, Wlo);
    xsplit_kernel<<<2048, 256>>>(x, Ahi, Alo, N);
    zero_int_kernel<<<(N + 255) / 256, 256>>>(deg, N);
    gemm_mma_kernel<<<gN, 256, SMEM_BYTES>>>(Ahi, Alo, nullptr, nullptr, Whi, Wlo,
        nullptr, Hf, nullptr, nullptr, nullptr, nullptr, nullptr, N, 0, tilesN, 0, 0);
    hist_kernel<<<(E + 255) / 256, 256>>>(dst, E, deg);
    scan1_kernel<<<nScanBlk, 1024>>>(deg, rowptr, bsum, N);
    scan2_kernel<<<1, 32>>>(bsum, nScanBlk);
    scan3_kernel<<<nScanBlk, 1024>>>(deg, rowptr, cur, bsum, N);
    fill_csr_kernel<<<(E + 255) / 256, 256>>>(src, dst, E, cur, eidx);

    // ---- trunk: agg -> GEMM -> agg -> GEMM -> agg ----
    agg_kernel<<<aggBlk, 256>>>(Hf, rowptr, eidx, b1, Ahi, Alo, nullptr, 1, 0, N);
    gemm_mma_kernel<<<gN, 256, SMEM_BYTES>>>(Ahi, Alo, nullptr, nullptr, Whi + 16384, Wlo + 16384,
        nullptr, Hf, nullptr, nullptr, nullptr, nullptr, nullptr, N, 0, tilesN, 0, 0);
    agg_kernel<<<aggBlk, 256>>>(Hf, rowptr, eidx, b2, Ahi, Alo, nullptr, 1, 0, N);
    gemm_mma_kernel<<<gN, 256, SMEM_BYTES>>>(Ahi, Alo, nullptr, nullptr, Whi + 2 * 16384, Wlo + 2 * 16384,
        nullptr, Hf, nullptr, nullptr, nullptr, nullptr, nullptr, N, 0, tilesN, 0, 0);
    agg_kernel<<<aggBlk, 256>>>(Hf, rowptr, eidx, b3, nullptr, nullptr, emb, 0, 1, N);

    // ---- link predictor ----
    // P1: gather-staging GEMM (A rows = emb[s]*emb[d]), epilogue -> Ahi/Alo (bias+relu)
    gemm_mma_kernel<<<gNE, 256, SMEM_BYTES>>>(nullptr, nullptr, emb, tedg, Whi + 3 * 16384, Wlo + 3 * 16384,
        pb1, nullptr, Ahi, Alo, nullptr, nullptr, nullptr, NE, 1, tilesNE, 1, 1);
    // P2: cp.async pipelined GEMM, fused final epilogue -> out
    gemm_mma_kernel<<<gNE, 256, SMEM_BYTES>>>(Ahi, Alo, nullptr, nullptr, Whi + 4 * 16384, Wlo + 4 * 16384,
        pb2, nullptr, nullptr, nullptr, P3, pb3, out, NE, 1, tilesNE, 0, 2);
}

// round 7
// speedup vs baseline: 1.0190x; 1.0190x over previous
#include <cuda_runtime.h>
#include <cuda_bf16.h>
#include <math.h>
#include <stdint.h>

// ---------------- problem constants ----------------
#define MAXN 50000
#define MAXE 800000
#define MAXNE 100000
#define D 128

// ---------------- device scratch ----------------
__device__ __nv_bfloat16 g_Ahi[(size_t)(MAXNE + 128) * D];
__device__ __nv_bfloat16 g_Alo[(size_t)(MAXNE + 128) * D];
__device__ float g_Hf [(size_t)MAXN * D];
__device__ float g_emb[(size_t)MAXN * D];
__device__ int   g_deg[MAXN];
__device__ int   g_rowptr[MAXN + 1];
__device__ int   g_cur[MAXN];
__device__ int   g_eidx[MAXE];
__device__ int   g_bsum[256];
__device__ __nv_bfloat16 g_Whi[5 * 16384];
__device__ __nv_bfloat16 g_Wlo[5 * 16384];

// ---------------- PTX helpers ----------------
__device__ __forceinline__ uint32_t smem_u32(const void* p) {
    uint32_t a;
    asm("{ .reg .u64 t; cvta.to.shared.u64 t, %1; cvt.u32.u64 %0, t; }" : "=r"(a) : "l"(p));
    return a;
}
__device__ __forceinline__ void ldsm4(uint32_t* r, uint32_t addr) {
    asm volatile("ldmatrix.sync.aligned.m8n8.x4.shared.b16 {%0,%1,%2,%3}, [%4];"
        : "=r"(r[0]), "=r"(r[1]), "=r"(r[2]), "=r"(r[3]) : "r"(addr));
}
__device__ __forceinline__ void mma16816(float* c, const uint32_t* a, const uint32_t* b) {
    asm volatile(
        "mma.sync.aligned.m16n8k16.row.col.f32.bf16.bf16.f32 "
        "{%0,%1,%2,%3}, {%4,%5,%6,%7}, {%8,%9}, {%0,%1,%2,%3};"
        : "+f"(c[0]), "+f"(c[1]), "+f"(c[2]), "+f"(c[3])
        : "r"(a[0]), "r"(a[1]), "r"(a[2]), "r"(a[3]), "r"(b[0]), "r"(b[1]));
}
__device__ __forceinline__ void cp_async16(uint32_t saddr, const void* gptr) {
    asm volatile("cp.async.cg.shared.global [%0], [%1], 16;" :: "r"(saddr), "l"(gptr));
}
#define CP_COMMIT() asm volatile("cp.async.commit_group;" ::: "memory")
template <int NN> __device__ __forceinline__ void cp_wait() {
    asm volatile("cp.async.wait_group %0;" :: "n"(NN) : "memory");
}
__device__ __forceinline__ void split2(float a, float b, uint32_t& hi, uint32_t& lo) {
    __nv_bfloat162 h = __floats2bfloat162_rn(a, b);
    float ra = a - __bfloat162float(h.x);
    float rb = b - __bfloat162float(h.y);
    __nv_bfloat162 l = __floats2bfloat162_rn(ra, rb);
    hi = *(uint32_t*)&h;
    lo = *(uint32_t*)&l;
}

// ---------------- CSR build kernels ----------------
__global__ void zero_int_kernel(int* p, int n) {
    for (int i = blockIdx.x * blockDim.x + threadIdx.x; i < n; i += gridDim.x * blockDim.x)
        p[i] = 0;
}
__global__ void hist_kernel(const int* __restrict__ dst, int E, int* __restrict__ deg) {
    for (int e = blockIdx.x * blockDim.x + threadIdx.x; e < E; e += gridDim.x * blockDim.x)
        atomicAdd(&deg[dst[e]], 1);
}
__global__ void scan1_kernel(const int* __restrict__ deg, int* __restrict__ rowptr,
                             int* __restrict__ bsum, int n) {
    __shared__ int wsum[32];
    int tid = threadIdx.x, lane = tid & 31, w = tid >> 5;
    int i = blockIdx.x * 1024 + tid;
    int v = (i < n) ? deg[i] : 0;
    int s = v;
    #pragma unroll
    for (int off = 1; off < 32; off <<= 1) {
        int t = __shfl_up_sync(0xFFFFFFFFu, s, off);
        if (lane >= off) s += t;
    }
    if (lane == 31) wsum[w] = s;
    __syncthreads();
    if (w == 0) {
        int ws = wsum[lane];
        #pragma unroll
        for (int off = 1; off < 32; off <<= 1) {
            int t = __shfl_up_sync(0xFFFFFFFFu, ws, off);
            if (lane >= off) ws += t;
        }
        wsum[lane] = ws;
    }
    __syncthreads();
    int prev = (w > 0) ? wsum[w - 1] : 0;
    int incl = prev + s;
    if (i < n) rowptr[i] = incl - v;
    if (tid == 1023) bsum[blockIdx.x] = incl;
}
__global__ void scan2_kernel(int* bsum, int nb) {
    int lane = threadIdx.x;
    int carry = 0;
    for (int base = 0; base < nb; base += 32) {
        int i = base + lane;
        int v = (i < nb) ? bsum[i] : 0;
        int s = v;
        #pragma unroll
        for (int off = 1; off < 32; off <<= 1) {
            int t = __shfl_up_sync(0xFFFFFFFFu, s, off);
            if (lane >= off) s += t;
        }
        if (i < nb) bsum[i] = carry + s - v;
        carry += __shfl_sync(0xFFFFFFFFu, s, 31);
    }
}
__global__ void scan3_kernel(const int* __restrict__ deg, int* __restrict__ rowptr,
                             int* __restrict__ cur, const int* __restrict__ bsum, int n) {
    int i = blockIdx.x * 1024 + threadIdx.x;
    if (i >= n) return;
    int val = rowptr[i] + bsum[blockIdx.x];
    rowptr[i] = val;
    cur[i] = val;
    if (i == n - 1) rowptr[n] = val + deg[n - 1];
}
__global__ void fill_csr_kernel(const int* __restrict__ src, const int* __restrict__ dst,
                                int E, int* __restrict__ cur, int* __restrict__ eidx) {
    for (int e = blockIdx.x * blockDim.x + threadIdx.x; e < E; e += gridDim.x * blockDim.x) {
        int d = dst[e];
        int p = atomicAdd(&cur[d], 1);
        eidx[p] = src[e];
    }
}

// ---------------- prep kernels ----------------
__global__ void prep_weights_kernel(const float* W1, const float* W2, const float* W3,
                                    const float* P1, const float* P2,
                                    __nv_bfloat16* hi, __nv_bfloat16* lo) {
    int idx = blockIdx.x * blockDim.x + threadIdx.x;
    if (idx >= 5 * 16384) return;
    int w = idx >> 14;
    int t = idx & 16383;
    int n = t >> 7;
    int k = t & 127;
    const float* Ws = (w == 0) ? W1 : (w == 1) ? W2 : (w == 2) ? W3 : (w == 3) ? P1 : P2;
    float v = Ws[(k << 7) | n];
    __nv_bfloat16 h = __float2bfloat16(v);
    float rem = v - __bfloat162float(h);
    hi[idx] = h;
    lo[idx] = __float2bfloat16(rem);
}
__global__ void xsplit_kernel(const float* __restrict__ x,
                              __nv_bfloat16* __restrict__ Ahi, __nv_bfloat16* __restrict__ Alo,
                              int N) {
    int n4 = N * 32;
    for (int idx = blockIdx.x * blockDim.x + threadIdx.x; idx < n4; idx += gridDim.x * blockDim.x) {
        float4 v = ((const float4*)x)[idx];
        uint2 hp, lp;
        split2(v.x, v.y, hp.x, lp.x);
        split2(v.z, v.w, hp.y, lp.y);
        *(uint2*)(Ahi + (size_t)idx * 4) = hp;
        *(uint2*)(Alo + (size_t)idx * 4) = lp;
    }
}

// ---------------- mma.sync GEMM: 512 threads, 16 warps (4m x 4n), warp tile 32x32 ----
#define ASTRIDE 136
#define ABUF (128 * ASTRIDE)
#define S_A0HI 0
#define S_A0LO ABUF
#define S_A1HI (2 * ABUF)
#define S_A1LO (3 * ABUF)
#define S_WHI  (4 * ABUF)
#define S_WLO  (5 * ABUF)
#define SMEM_ELEMS (6 * ABUF)
#define SMEM_BYTES (SMEM_ELEMS * 2 + (1024 + 256 + 8) * 4)

// stagemode: 0 = cp.async from Ahi/Alo; 1 = ALU gather products (embf, tedg)
// epimode:   0 = fp32 C (+bias/relu); 1 = bf16 hi/lo out (+bias/relu); 2 = fused final
__global__ void __launch_bounds__(512, 1)
gemm_mma_kernel(const __nv_bfloat16* __restrict__ Ahi, const __nv_bfloat16* __restrict__ Alo,
                const float* __restrict__ embf, const int* __restrict__ tedg,
                const __nv_bfloat16* __restrict__ Wt_hi, const __nv_bfloat16* __restrict__ Wt_lo,
                const float* __restrict__ bias, float* __restrict__ Cf,
                __nv_bfloat16* __restrict__ OutHi, __nv_bfloat16* __restrict__ OutLo,
                const float* __restrict__ P3, const float* __restrict__ pb3,
                float* __restrict__ outF,
                int M, int relu, int numTiles, int stagemode, int epimode) {
    extern __shared__ __nv_bfloat16 sm[];
    uint32_t sbase = smem_u32(sm);
    float* fpart = (float*)(sm + SMEM_ELEMS);     // [128][4][2]
    float* fP3 = fpart + 1024;
    float* fpb3 = fP3 + 256;
    int tid = threadIdx.x, wid = tid >> 5, lane = tid & 31;

    // ---- stage Wt hi/lo (once per CTA, padded rows) ----
    {
        const uint4* wh = (const uint4*)Wt_hi;
        const uint4* wl = (const uint4*)Wt_lo;
        for (int i = tid; i < 2048; i += 512) {
            int r = i >> 4, c = i & 15;
            *(uint4*)(sm + S_WHI + r * ASTRIDE + c * 8) = wh[i];
            *(uint4*)(sm + S_WLO + r * ASTRIDE + c * 8) = wl[i];
        }
        if (epimode == 2) {
            if (tid < 256) fP3[tid] = P3[tid];
            if (tid < 2) fpb3[tid] = pb3[tid];
        }
    }

    int mwid = wid >> 2;                          // 0..3
    int nwid = wid & 3;                           // 0..3
    int mrow0 = mwid << 5;                        // 0,32,64,96
    int ncol0 = nwid << 5;                        // 0,32,64,96

    uint32_t aRel = (uint32_t)(mrow0 + (lane & 15)) * (ASTRIDE * 2)
                  + (uint32_t)(((lane >> 4) << 3) * 2);
    uint32_t bN = (uint32_t)(ncol0 + ((lane >> 4) << 3) + (lane & 7));
    uint32_t bKB = (uint32_t)((((lane >> 3) & 1) << 3) * 2);
    uint32_t bHiBase = sbase + (S_WHI * 2) + bN * (ASTRIDE * 2) + bKB;
    uint32_t bLoBase = bHiBase + (S_WLO - S_WHI) * 2;

    auto stage = [&](int tile, int buf) {
        int row0 = tile << 7;
        uint32_t baseHi = (buf ? S_A1HI : S_A0HI);
        uint32_t baseLo = (buf ? S_A1LO : S_A0LO);
        if (stagemode == 0) {
            #pragma unroll
            for (int it = 0; it < 4; it++) {
                int idx = it * 512 + tid;          // 0..2047
                int r = idx >> 4, c = idx & 15;
                size_t goff = (size_t)(row0 + r) * D + c * 8;
                uint32_t soff = (r * ASTRIDE + c * 8) * 2;
                cp_async16(sbase + baseHi * 2 + soff, Ahi + goff);
                cp_async16(sbase + baseLo * 2 + soff, Alo + goff);
            }
            CP_COMMIT();
        } else {
            #pragma unroll
            for (int it = 0; it < 8; it++) {
                int idx = it * 512 + tid;
                int r = idx >> 5;
                int c4 = idx & 31;
                int grow = row0 + r;
                float4 v;
                if (grow < M) {
                    int s = tedg[2 * grow];
                    int d = tedg[2 * grow + 1];
                    float4 a = *(const float4*)(embf + (size_t)s * D + c4 * 4);
                    float4 b = *(const float4*)(embf + (size_t)d * D + c4 * 4);
                    v = make_float4(a.x * b.x, a.y * b.y, a.z * b.z, a.w * b.w);
                } else {
                    v = make_float4(0.f, 0.f, 0.f, 0.f);
                }
                uint2 hp, lp;
                split2(v.x, v.y, hp.x, lp.x);
                split2(v.z, v.w, hp.y, lp.y);
                *(uint2*)(sm + baseHi + r * ASTRIDE + c4 * 4) = hp;
                *(uint2*)(sm + baseLo + r * ASTRIDE + c4 * 4) = lp;
            }
        }
    };

    int t = blockIdx.x;
    if (t < numTiles) stage(t, 0);
    int parity = 0;
    for (; t < numTiles; t += gridDim.x, parity ^= 1) {
        int nxt = t + gridDim.x;
        if (nxt < numTiles) stage(nxt, parity ^ 1);
        if (stagemode == 0) {
            if (nxt < numTiles) cp_wait<1>(); else cp_wait<0>();
        }
        __syncthreads();

        int row0 = t << 7;
        uint32_t abase2 = (parity ? S_A1HI : S_A0HI) * 2;
        uint32_t aHi0 = sbase + abase2 + aRel;
        uint32_t aHi1 = aHi0 + 16 * (ASTRIDE * 2);
        uint32_t aLo0 = aHi0 + ABUF * 2;
        uint32_t aLo1 = aHi1 + ABUF * 2;

        float acc[2][4][4];
        #pragma unroll
        for (int mt = 0; mt < 2; mt++)
            #pragma unroll
            for (int nt = 0; nt < 4; nt++)
                #pragma unroll
                for (int q = 0; q < 4; q++) acc[mt][nt][q] = 0.0f;

        #pragma unroll
        for (int ks = 0; ks < 8; ks++) {
            uint32_t koffB = (uint32_t)(ks * 32);
            uint32_t ah[2][4], al[2][4];
            ldsm4(ah[0], aHi0 + koffB);
            ldsm4(ah[1], aHi1 + koffB);
            ldsm4(al[0], aLo0 + koffB);
            ldsm4(al[1], aLo1 + koffB);
            uint32_t bh[4][2], bl[4][2];
            #pragma unroll
            for (int np = 0; np < 2; np++) {
                uint32_t r4[4];
                ldsm4(r4, bHiBase + (uint32_t)(np * 16 * ASTRIDE * 2) + koffB);
                bh[2 * np][0] = r4[0]; bh[2 * np][1] = r4[1];
                bh[2 * np + 1][0] = r4[2]; bh[2 * np + 1][1] = r4[3];
                ldsm4(r4, bLoBase + (uint32_t)(np * 16 * ASTRIDE * 2) + koffB);
                bl[2 * np][0] = r4[0]; bl[2 * np][1] = r4[1];
                bl[2 * np + 1][0] = r4[2]; bl[2 * np + 1][1] = r4[3];
            }
            #pragma unroll
            for (int mt = 0; mt < 2; mt++)
                #pragma unroll
                for (int nt = 0; nt < 4; nt++) {
                    mma16816(acc[mt][nt], ah[mt], bh[nt]);
                    mma16816(acc[mt][nt], ah[mt], bl[nt]);
                    mma16816(acc[mt][nt], al[mt], bh[nt]);
                }
        }

        int cbase = ncol0 + ((lane & 3) << 1);

        if (epimode == 2) {
            // per-warp partial dot with P3 over its 32 cols
            float q0s[4], q1s[4];
            #pragma unroll
            for (int mt = 0; mt < 2; mt++) {
                #pragma unroll
                for (int half = 0; half < 2; half++) {
                    float q0 = 0.f, q1 = 0.f;
                    #pragma unroll
                    for (int nt = 0; nt < 4; nt++) {
                        int col = cbase + nt * 8;
                        float z0 = fmaxf(acc[mt][nt][2 * half] + bias[col], 0.f);
                        float z1 = fmaxf(acc[mt][nt][2 * half + 1] + bias[col + 1], 0.f);
                        q0 += z0 * fP3[2 * col] + z1 * fP3[2 * (col + 1)];
                        q1 += z0 * fP3[2 * col + 1] + z1 * fP3[2 * (col + 1) + 1];
                    }
                    q0 += __shfl_xor_sync(0xFFFFFFFFu, q0, 1);
                    q0 += __shfl_xor_sync(0xFFFFFFFFu, q0, 2);
                    q1 += __shfl_xor_sync(0xFFFFFFFFu, q1, 1);
                    q1 += __shfl_xor_sync(0xFFFFFFFFu, q1, 2);
                    q0s[mt * 2 + half] = q0;
                    q1s[mt * 2 + half] = q1;
                    if (nwid != 0 && (lane & 3) == 0) {
                        int rl = mrow0 + mt * 16 + half * 8 + (lane >> 2);
                        fpart[rl * 8 + nwid * 2]     = q0;
                        fpart[rl * 8 + nwid * 2 + 1] = q1;
                    }
                }
            }
            __syncthreads();
            if (nwid == 0 && (lane & 3) == 0) {
                #pragma unroll
                for (int mt = 0; mt < 2; mt++) {
                    #pragma unroll
                    for (int half = 0; half < 2; half++) {
                        int rl = mrow0 + mt * 16 + half * 8 + (lane >> 2);
                        int gr = row0 + rl;
                        if (gr < M) {
                            float z0 = q0s[mt * 2 + half] + fpb3[0];
                            float z1 = q1s[mt * 2 + half] + fpb3[1];
                            #pragma unroll
                            for (int nw = 1; nw < 4; nw++) {
                                z0 += fpart[rl * 8 + nw * 2];
                                z1 += fpart[rl * 8 + nw * 2 + 1];
                            }
                            float nrm = fmaxf(sqrtf(z0 * z0 + z1 * z1), 1e-12f);
                            z0 /= nrm; z1 /= nrm;
                            float mm = fmaxf(z0, z1);
                            float lse = mm + logf(expf(z0 - mm) + expf(z1 - mm));
                            outF[2 * gr]     = z0 - lse;
                            outF[2 * gr + 1] = z1 - lse;
                        }
                    }
                }
            }
        } else if (epimode == 1) {
            int rbase = row0 + mrow0 + (lane >> 2);
            #pragma unroll
            for (int mt = 0; mt < 2; mt++) {
                #pragma unroll
                for (int half = 0; half < 2; half++) {
                    int gr = rbase + mt * 16 + half * 8;
                    if (gr >= M) continue;
                    #pragma unroll
                    for (int nt = 0; nt < 4; nt++) {
                        int col = cbase + nt * 8;
                        float o0 = fmaxf(acc[mt][nt][2 * half] + bias[col], 0.f);
                        float o1 = fmaxf(acc[mt][nt][2 * half + 1] + bias[col + 1], 0.f);
                        uint32_t hp, lp;
                        split2(o0, o1, hp, lp);
                        *(uint32_t*)(OutHi + (size_t)gr * D + col) = hp;
                        *(uint32_t*)(OutLo + (size_t)gr * D + col) = lp;
                    }
                }
            }
        } else {
            int rbase = row0 + mrow0 + (lane >> 2);
            #pragma unroll
            for (int mt = 0; mt < 2; mt++) {
                #pragma unroll
                for (int half = 0; half < 2; half++) {
                    int gr = rbase + mt * 16 + half * 8;
                    if (gr >= M) continue;
                    float* cp = Cf + (size_t)gr * D;
                    #pragma unroll
                    for (int nt = 0; nt < 4; nt++) {
                        int col = cbase + nt * 8;
                        float o0 = acc[mt][nt][2 * half];
                        float o1 = acc[mt][nt][2 * half + 1];
                        if (bias) { o0 += bias[col]; o1 += bias[col + 1]; }
                        if (relu) { o0 = fmaxf(o0, 0.f); o1 = fmaxf(o1, 0.f); }
                        *(float2*)(cp + col) = make_float2(o0, o1);
                    }
                }
            }
        }
        __syncthreads();
    }
}

// ---------------- aggregation: warp-per-dst; outmode 0 = bf16 hi/lo, 1 = fp32 ----
__global__ void agg_kernel(const float* __restrict__ H, const int* __restrict__ rowptr,
                           const int* __restrict__ eidx, const float* __restrict__ bias,
                           __nv_bfloat16* __restrict__ OutHi, __nv_bfloat16* __restrict__ OutLo,
                           float* __restrict__ OutF,
                           int relu, int outmode, int N) {
    int gw = (blockIdx.x * blockDim.x + threadIdx.x) >> 5;
    int lane = threadIdx.x & 31;
    if (gw >= N) return;
    int beg = rowptr[gw], end = rowptr[gw + 1];
    float4 acc = make_float4(0.f, 0.f, 0.f, 0.f);
    for (int j0 = beg; j0 < end; j0 += 32) {
        int cnt = min(32, end - j0);
        int e = (lane < cnt) ? eidx[j0 + lane] : 0;
        for (int t = 0; t < cnt; t++) {
            int s = __shfl_sync(0xFFFFFFFFu, e, t);
            float4 v = *(const float4*)(H + (size_t)s * D + (lane << 2));
            acc.x += v.x; acc.y += v.y; acc.z += v.z; acc.w += v.w;
        }
    }
    float4 bv = *(const float4*)(bias + (lane << 2));
    acc.x += bv.x; acc.y += bv.y; acc.z += bv.z; acc.w += bv.w;
    if (relu) {
        acc.x = fmaxf(acc.x, 0.f); acc.y = fmaxf(acc.y, 0.f);
        acc.z = fmaxf(acc.z, 0.f); acc.w = fmaxf(acc.w, 0.f);
    }
    if (outmode == 0) {
        uint2 hp, lp;
        split2(acc.x, acc.y, hp.x, lp.x);
        split2(acc.z, acc.w, hp.y, lp.y);
        *(uint2*)(OutHi + (size_t)gw * D + (lane << 2)) = hp;
        *(uint2*)(OutLo + (size_t)gw * D + (lane << 2)) = lp;
    } else {
        *(float4*)(OutF + (size_t)gw * D + (lane << 2)) = acc;
    }
}

// ---------------- launch ----------------
extern "C" void kernel_launch(void* const* d_in, const int* in_sizes, int n_in,
                              void* d_out, int out_size) {
    const float* x    = (const float*)d_in[0];
    const int*   adj  = (const int*)d_in[1];
    const int*   tedg = (const int*)d_in[2];
    const float* W1 = (const float*)d_in[3];  const float* b1  = (const float*)d_in[4];
    const float* W2 = (const float*)d_in[5];  const float* b2  = (const float*)d_in[6];
    const float* W3 = (const float*)d_in[7];  const float* b3  = (const float*)d_in[8];
    const float* P1 = (const float*)d_in[9];  const float* pb1 = (const float*)d_in[10];
    const float* P2 = (const float*)d_in[11]; const float* pb2 = (const float*)d_in[12];
    const float* P3 = (const float*)d_in[13]; const float* pb3 = (const float*)d_in[14];
    float* out = (float*)d_out;

    int N  = in_sizes[0] / D;
    int E  = in_sizes[1] / 2;
    int NE = in_sizes[2] / 2;

    cudaFuncSetAttribute((const void*)gemm_mma_kernel,
                         cudaFuncAttributeMaxDynamicSharedMemorySize, SMEM_BYTES);

    __nv_bfloat16 *Ahi, *Alo, *Whi, *Wlo;
    float *Hf, *emb;
    int *deg, *rowptr, *cur, *eidx, *bsum;
    cudaGetSymbolAddress((void**)&Ahi, g_Ahi);
    cudaGetSymbolAddress((void**)&Alo, g_Alo);
    cudaGetSymbolAddress((void**)&Hf,  g_Hf);
    cudaGetSymbolAddress((void**)&emb, g_emb);
    cudaGetSymbolAddress((void**)&deg,    g_deg);
    cudaGetSymbolAddress((void**)&rowptr, g_rowptr);
    cudaGetSymbolAddress((void**)&cur,    g_cur);
    cudaGetSymbolAddress((void**)&eidx,   g_eidx);
    cudaGetSymbolAddress((void**)&bsum,   g_bsum);
    cudaGetSymbolAddress((void**)&Whi,  g_Whi);
    cudaGetSymbolAddress((void**)&Wlo,  g_Wlo);

    const int* src = adj;
    const int* dst = adj + E;

    int nScanBlk = (N + 1023) / 1024;
    int tilesN  = (N + 127) / 128;
    int tilesNE = (NE + 127) / 128;
    int gN  = tilesN  < 148 ? tilesN  : 148;
    int gNE = tilesNE < 148 ? tilesNE : 148;
    int aggBlk = (N * 32 + 255) / 256;

    // ---- prep + L1 GEMM early, CSR chain after ----
    prep_weights_kernel<<<(5 * 16384 + 255) / 256, 256>>>(W1, W2, W3, P1, P2, Whi, Wlo);
    xsplit_kernel<<<2048, 256>>>(x, Ahi, Alo, N);
    zero_int_kernel<<<(N + 255) / 256, 256>>>(deg, N);
    gemm_mma_kernel<<<gN, 512, SMEM_BYTES>>>(Ahi, Alo, nullptr, nullptr, Whi, Wlo,
        nullptr, Hf, nullptr, nullptr, nullptr, nullptr, nullptr, N, 0, tilesN, 0, 0);
    hist_kernel<<<(E + 255) / 256, 256>>>(dst, E, deg);
    scan1_kernel<<<nScanBlk, 1024>>>(deg, rowptr, bsum, N);
    scan2_kernel<<<1, 32>>>(bsum, nScanBlk);
    scan3_kernel<<<nScanBlk, 1024>>>(deg, rowptr, cur, bsum, N);
    fill_csr_kernel<<<(E + 255) / 256, 256>>>(src, dst, E, cur, eidx);

    // ---- trunk ----
    agg_kernel<<<aggBlk, 256>>>(Hf, rowptr, eidx, b1, Ahi, Alo, nullptr, 1, 0, N);
    gemm_mma_kernel<<<gN, 512, SMEM_BYTES>>>(Ahi, Alo, nullptr, nullptr, Whi + 16384, Wlo + 16384,
        nullptr, Hf, nullptr, nullptr, nullptr, nullptr, nullptr, N, 0, tilesN, 0, 0);
    agg_kernel<<<aggBlk, 256>>>(Hf, rowptr, eidx, b2, Ahi, Alo, nullptr, 1, 0, N);
    gemm_mma_kernel<<<gN, 512, SMEM_BYTES>>>(Ahi, Alo, nullptr, nullptr, Whi + 2 * 16384, Wlo + 2 * 16384,
        nullptr, Hf, nullptr, nullptr, nullptr, nullptr, nullptr, N, 0, tilesN, 0, 0);
    agg_kernel<<<aggBlk, 256>>>(Hf, rowptr, eidx, b3, nullptr, nullptr, emb, 0, 1, N);

    // ---- link predictor ----
    gemm_mma_kernel<<<gNE, 512, SMEM_BYTES>>>(nullptr, nullptr, emb, tedg, Whi + 3 * 16384, Wlo + 3 * 16384,
        pb1, nullptr, Ahi, Alo, nullptr, nullptr, nullptr, NE, 1, tilesNE, 1, 1);
    gemm_mma_kernel<<<gNE, 512, SMEM_BYTES>>>(Ahi, Alo, nullptr, nullptr, Whi + 4 * 16384, Wlo + 4 * 16384,
        pb2, nullptr, nullptr, nullptr, P3, pb3, out, NE, 1, tilesNE, 0, 2);
}

// round 8
// speedup vs baseline: 1.0492x; 1.0297x over previous
#include <cuda_runtime.h>
#include <cuda_bf16.h>
#include <math.h>
#include <stdint.h>

// ---------------- problem constants ----------------
#define MAXN 50000
#define MAXE 800000
#define MAXNE 100000
#define D 128

// ---------------- device scratch ----------------
__device__ __nv_bfloat16 g_Ahi[(size_t)(MAXNE + 128) * D];
__device__ __nv_bfloat16 g_Alo[(size_t)(MAXNE + 128) * D];
__device__ float g_Hf [(size_t)MAXN * D];
__device__ float g_emb[(size_t)MAXN * D];
__device__ int   g_deg[MAXN];
__device__ int   g_rowptr[MAXN + 1];
__device__ int   g_cur[MAXN];
__device__ int   g_eidx[MAXE];
__device__ int   g_bsum[256];
__device__ __nv_bfloat16 g_Whi[5 * 16384];
__device__ __nv_bfloat16 g_Wlo[5 * 16384];

// ---------------- PTX helpers ----------------
__device__ __forceinline__ uint32_t smem_u32(const void* p) {
    uint32_t a;
    asm("{ .reg .u64 t; cvta.to.shared.u64 t, %1; cvt.u32.u64 %0, t; }" : "=r"(a) : "l"(p));
    return a;
}
__device__ __forceinline__ void ldsm4(uint32_t* r, uint32_t addr) {
    asm volatile("ldmatrix.sync.aligned.m8n8.x4.shared.b16 {%0,%1,%2,%3}, [%4];"
        : "=r"(r[0]), "=r"(r[1]), "=r"(r[2]), "=r"(r[3]) : "r"(addr));
}
__device__ __forceinline__ void mma16816(float* c, const uint32_t* a, const uint32_t* b) {
    asm volatile(
        "mma.sync.aligned.m16n8k16.row.col.f32.bf16.bf16.f32 "
        "{%0,%1,%2,%3}, {%4,%5,%6,%7}, {%8,%9}, {%0,%1,%2,%3};"
        : "+f"(c[0]), "+f"(c[1]), "+f"(c[2]), "+f"(c[3])
        : "r"(a[0]), "r"(a[1]), "r"(a[2]), "r"(a[3]), "r"(b[0]), "r"(b[1]));
}
__device__ __forceinline__ void cp_async16(uint32_t saddr, const void* gptr) {
    asm volatile("cp.async.cg.shared.global [%0], [%1], 16;" :: "r"(saddr), "l"(gptr));
}
#define CP_COMMIT() asm volatile("cp.async.commit_group;" ::: "memory")
template <int NN> __device__ __forceinline__ void cp_wait() {
    asm volatile("cp.async.wait_group %0;" :: "n"(NN) : "memory");
}
__device__ __forceinline__ void split2(float a, float b, uint32_t& hi, uint32_t& lo) {
    __nv_bfloat162 h = __floats2bfloat162_rn(a, b);
    float ra = a - __bfloat162float(h.x);
    float rb = b - __bfloat162float(h.y);
    __nv_bfloat162 l = __floats2bfloat162_rn(ra, rb);
    hi = *(uint32_t*)&h;
    lo = *(uint32_t*)&l;
}

// ---------------- CSR build kernels ----------------
__global__ void zero_int_kernel(int* p, int n) {
    for (int i = blockIdx.x * blockDim.x + threadIdx.x; i < n; i += gridDim.x * blockDim.x)
        p[i] = 0;
}
__global__ void hist_kernel(const int* __restrict__ dst, int E, int* __restrict__ deg) {
    for (int e = blockIdx.x * blockDim.x + threadIdx.x; e < E; e += gridDim.x * blockDim.x)
        atomicAdd(&deg[dst[e]], 1);
}
__global__ void scan1_kernel(const int* __restrict__ deg, int* __restrict__ rowptr,
                             int* __restrict__ bsum, int n) {
    __shared__ int wsum[32];
    int tid = threadIdx.x, lane = tid & 31, w = tid >> 5;
    int i = blockIdx.x * 1024 + tid;
    int v = (i < n) ? deg[i] : 0;
    int s = v;
    #pragma unroll
    for (int off = 1; off < 32; off <<= 1) {
        int t = __shfl_up_sync(0xFFFFFFFFu, s, off);
        if (lane >= off) s += t;
    }
    if (lane == 31) wsum[w] = s;
    __syncthreads();
    if (w == 0) {
        int ws = wsum[lane];
        #pragma unroll
        for (int off = 1; off < 32; off <<= 1) {
            int t = __shfl_up_sync(0xFFFFFFFFu, ws, off);
            if (lane >= off) ws += t;
        }
        wsum[lane] = ws;
    }
    __syncthreads();
    int prev = (w > 0) ? wsum[w - 1] : 0;
    int incl = prev + s;
    if (i < n) rowptr[i] = incl - v;
    if (tid == 1023) bsum[blockIdx.x] = incl;
}
__global__ void scan2_kernel(int* bsum, int nb) {
    int lane = threadIdx.x;
    int carry = 0;
    for (int base = 0; base < nb; base += 32) {
        int i = base + lane;
        int v = (i < nb) ? bsum[i] : 0;
        int s = v;
        #pragma unroll
        for (int off = 1; off < 32; off <<= 1) {
            int t = __shfl_up_sync(0xFFFFFFFFu, s, off);
            if (lane >= off) s += t;
        }
        if (i < nb) bsum[i] = carry + s - v;
        carry += __shfl_sync(0xFFFFFFFFu, s, 31);
    }
}
__global__ void scan3_kernel(const int* __restrict__ deg, int* __restrict__ rowptr,
                             int* __restrict__ cur, const int* __restrict__ bsum, int n) {
    int i = blockIdx.x * 1024 + threadIdx.x;
    if (i >= n) return;
    int val = rowptr[i] + bsum[blockIdx.x];
    rowptr[i] = val;
    cur[i] = val;
    if (i == n - 1) rowptr[n] = val + deg[n - 1];
}
__global__ void fill_csr_kernel(const int* __restrict__ src, const int* __restrict__ dst,
                                int E, int* __restrict__ cur, int* __restrict__ eidx) {
    for (int e = blockIdx.x * blockDim.x + threadIdx.x; e < E; e += gridDim.x * blockDim.x) {
        int d = dst[e];
        int p = atomicAdd(&cur[d], 1);
        eidx[p] = src[e];
    }
}

// ---------------- prep kernels ----------------
__global__ void prep_weights_kernel(const float* W1, const float* W2, const float* W3,
                                    const float* P1, const float* P2,
                                    __nv_bfloat16* hi, __nv_bfloat16* lo) {
    int idx = blockIdx.x * blockDim.x + threadIdx.x;
    if (idx >= 5 * 16384) return;
    int w = idx >> 14;
    int t = idx & 16383;
    int n = t >> 7;
    int k = t & 127;
    const float* Ws = (w == 0) ? W1 : (w == 1) ? W2 : (w == 2) ? W3 : (w == 3) ? P1 : P2;
    float v = Ws[(k << 7) | n];
    __nv_bfloat16 h = __float2bfloat16(v);
    float rem = v - __bfloat162float(h);
    hi[idx] = h;
    lo[idx] = __float2bfloat16(rem);
}
__global__ void xsplit_kernel(const float* __restrict__ x,
                              __nv_bfloat16* __restrict__ Ahi, __nv_bfloat16* __restrict__ Alo,
                              int N) {
    int n4 = N * 32;
    for (int idx = blockIdx.x * blockDim.x + threadIdx.x; idx < n4; idx += gridDim.x * blockDim.x) {
        float4 v = ((const float4*)x)[idx];
        uint2 hp, lp;
        split2(v.x, v.y, hp.x, lp.x);
        split2(v.z, v.w, hp.y, lp.y);
        *(uint2*)(Ahi + (size_t)idx * 4) = hp;
        *(uint2*)(Alo + (size_t)idx * 4) = lp;
    }
}

// ---------------- mma.sync GEMM: 64x128 CTA tile, 8 warps (2m x 4n), 2 CTAs/SM ----
#define ASTRIDE 136
#define TM 64                              // CTA tile rows
#define ABUF (TM * ASTRIDE)                // 8704 elems per A array
#define WBUF (128 * ASTRIDE)               // 17408 elems per W array
#define S_AHI 0
#define S_ALO ABUF
#define S_WHI (2 * ABUF)
#define S_WLO (2 * ABUF + WBUF)
#define SMEM_ELEMS (2 * ABUF + 2 * WBUF)   // 52224 bf16 = 104448 B
#define SMEM_BYTES (SMEM_ELEMS * 2 + (512 + 256 + 8) * 4)   // ~107.6 KB

// stagemode: 0 = cp.async from Ahi/Alo; 1 = ALU gather products (embf, tedg)
// epimode:   0 = fp32 C (+bias/relu); 1 = bf16 hi/lo out (+bias/relu); 2 = fused final
__global__ void __launch_bounds__(256, 2)
gemm_mma_kernel(const __nv_bfloat16* __restrict__ Ahi, const __nv_bfloat16* __restrict__ Alo,
                const float* __restrict__ embf, const int* __restrict__ tedg,
                const __nv_bfloat16* __restrict__ Wt_hi, const __nv_bfloat16* __restrict__ Wt_lo,
                const float* __restrict__ bias, float* __restrict__ Cf,
                __nv_bfloat16* __restrict__ OutHi, __nv_bfloat16* __restrict__ OutLo,
                const float* __restrict__ P3, const float* __restrict__ pb3,
                float* __restrict__ outF,
                int M, int relu, int numTiles, int stagemode, int epimode) {
    extern __shared__ __nv_bfloat16 sm[];
    uint32_t sbase = smem_u32(sm);
    float* fpart = (float*)(sm + SMEM_ELEMS);     // [64][4][2]
    float* fP3 = fpart + 512;
    float* fpb3 = fP3 + 256;
    int tid = threadIdx.x, wid = tid >> 5, lane = tid & 31;

    // ---- stage Wt hi/lo (once per CTA, padded rows) ----
    {
        const uint4* wh = (const uint4*)Wt_hi;
        const uint4* wl = (const uint4*)Wt_lo;
        for (int i = tid; i < 2048; i += 256) {
            int r = i >> 4, c = i & 15;
            *(uint4*)(sm + S_WHI + r * ASTRIDE + c * 8) = wh[i];
            *(uint4*)(sm + S_WLO + r * ASTRIDE + c * 8) = wl[i];
        }
        if (epimode == 2) {
            fP3[tid] = P3[tid];
            if (tid < 2) fpb3[tid] = pb3[tid];
        }
    }

    int mwid = wid >> 2;                          // 0..1
    int nwid = wid & 3;                           // 0..3
    int mrow0 = mwid << 5;                        // 0,32
    int ncol0 = nwid << 5;                        // 0,32,64,96

    uint32_t aRel = (uint32_t)(mrow0 + (lane & 15)) * (ASTRIDE * 2)
                  + (uint32_t)(((lane >> 4) << 3) * 2);
    uint32_t aHi0 = sbase + (S_AHI * 2) + aRel;
    uint32_t aHi1 = aHi0 + 16 * (ASTRIDE * 2);
    uint32_t aLo0 = aHi0 + ABUF * 2;
    uint32_t aLo1 = aHi1 + ABUF * 2;

    uint32_t bN = (uint32_t)(ncol0 + ((lane >> 4) << 3) + (lane & 7));
    uint32_t bKB = (uint32_t)((((lane >> 3) & 1) << 3) * 2);
    uint32_t bHiBase = sbase + (S_WHI * 2) + bN * (ASTRIDE * 2) + bKB;
    uint32_t bLoBase = bHiBase + WBUF * 2;

    for (int t = blockIdx.x; t < numTiles; t += gridDim.x) {
        int row0 = t * TM;

        // ---- stage A tile (64 x 128) ----
        if (stagemode == 0) {
            #pragma unroll
            for (int it = 0; it < 4; it++) {
                int idx = it * 256 + tid;          // 0..1023
                int r = idx >> 4, c = idx & 15;
                size_t goff = (size_t)(row0 + r) * D + c * 8;
                uint32_t soff = (r * ASTRIDE + c * 8) * 2;
                cp_async16(sbase + (S_AHI * 2) + soff, Ahi + goff);
                cp_async16(sbase + (S_ALO * 2) + soff, Alo + goff);
            }
            CP_COMMIT();
            cp_wait<0>();
        } else {
            #pragma unroll
            for (int it = 0; it < 8; it++) {
                int idx = it * 256 + tid;          // 0..2047
                int r = idx >> 5;
                int c4 = idx & 31;
                int grow = row0 + r;
                float4 v;
                if (grow < M) {
                    int s = tedg[2 * grow];
                    int d = tedg[2 * grow + 1];
                    float4 a = *(const float4*)(embf + (size_t)s * D + c4 * 4);
                    float4 b = *(const float4*)(embf + (size_t)d * D + c4 * 4);
                    v = make_float4(a.x * b.x, a.y * b.y, a.z * b.z, a.w * b.w);
                } else {
                    v = make_float4(0.f, 0.f, 0.f, 0.f);
                }
                uint2 hp, lp;
                split2(v.x, v.y, hp.x, lp.x);
                split2(v.z, v.w, hp.y, lp.y);
                *(uint2*)(sm + S_AHI + r * ASTRIDE + c4 * 4) = hp;
                *(uint2*)(sm + S_ALO + r * ASTRIDE + c4 * 4) = lp;
            }
        }
        __syncthreads();

        float acc[2][4][4];
        #pragma unroll
        for (int mt = 0; mt < 2; mt++)
            #pragma unroll
            for (int nt = 0; nt < 4; nt++)
                #pragma unroll
                for (int q = 0; q < 4; q++) acc[mt][nt][q] = 0.0f;

        #pragma unroll
        for (int ks = 0; ks < 8; ks++) {
            uint32_t koffB = (uint32_t)(ks * 32);
            uint32_t ah[2][4], al[2][4];
            ldsm4(ah[0], aHi0 + koffB);
            ldsm4(ah[1], aHi1 + koffB);
            ldsm4(al[0], aLo0 + koffB);
            ldsm4(al[1], aLo1 + koffB);
            uint32_t bh[4][2], bl[4][2];
            #pragma unroll
            for (int np = 0; np < 2; np++) {
                uint32_t r4[4];
                ldsm4(r4, bHiBase + (uint32_t)(np * 16 * ASTRIDE * 2) + koffB);
                bh[2 * np][0] = r4[0]; bh[2 * np][1] = r4[1];
                bh[2 * np + 1][0] = r4[2]; bh[2 * np + 1][1] = r4[3];
                ldsm4(r4, bLoBase + (uint32_t)(np * 16 * ASTRIDE * 2) + koffB);
                bl[2 * np][0] = r4[0]; bl[2 * np][1] = r4[1];
                bl[2 * np + 1][0] = r4[2]; bl[2 * np + 1][1] = r4[3];
            }
            #pragma unroll
            for (int mt = 0; mt < 2; mt++)
                #pragma unroll
                for (int nt = 0; nt < 4; nt++) {
                    mma16816(acc[mt][nt], ah[mt], bh[nt]);
                    mma16816(acc[mt][nt], ah[mt], bl[nt]);
                    mma16816(acc[mt][nt], al[mt], bh[nt]);
                }
        }

        int cbase = ncol0 + ((lane & 3) << 1);

        if (epimode == 2) {
            float q0s[2], q1s[2];
            #pragma unroll
            for (int mh = 0; mh < 2; mh++) {       // flattened mt(=mh? no) — here mt loop
                ;
            }
            // mt in {0,1} x half in {0,1} -> 4 rows handled; store per (mt,half)
            float q0a[4], q1a[4];
            #pragma unroll
            for (int mt = 0; mt < 2; mt++) {
                #pragma unroll
                for (int half = 0; half < 2; half++) {
                    float q0 = 0.f, q1 = 0.f;
                    #pragma unroll
                    for (int nt = 0; nt < 4; nt++) {
                        int col = cbase + nt * 8;
                        float z0 = fmaxf(acc[mt][nt][2 * half] + bias[col], 0.f);
                        float z1 = fmaxf(acc[mt][nt][2 * half + 1] + bias[col + 1], 0.f);
                        q0 += z0 * fP3[2 * col] + z1 * fP3[2 * (col + 1)];
                        q1 += z0 * fP3[2 * col + 1] + z1 * fP3[2 * (col + 1) + 1];
                    }
                    q0 += __shfl_xor_sync(0xFFFFFFFFu, q0, 1);
                    q0 += __shfl_xor_sync(0xFFFFFFFFu, q0, 2);
                    q1 += __shfl_xor_sync(0xFFFFFFFFu, q1, 1);
                    q1 += __shfl_xor_sync(0xFFFFFFFFu, q1, 2);
                    q0a[mt * 2 + half] = q0;
                    q1a[mt * 2 + half] = q1;
                    if (nwid != 0 && (lane & 3) == 0) {
                        int rl = mrow0 + mt * 16 + half * 8 + (lane >> 2);
                        fpart[rl * 8 + nwid * 2]     = q0;
                        fpart[rl * 8 + nwid * 2 + 1] = q1;
                    }
                }
            }
            __syncthreads();
            if (nwid == 0 && (lane & 3) == 0) {
                #pragma unroll
                for (int mt = 0; mt < 2; mt++) {
                    #pragma unroll
                    for (int half = 0; half < 2; half++) {
                        int rl = mrow0 + mt * 16 + half * 8 + (lane >> 2);
                        int gr = row0 + rl;
                        if (gr < M) {
                            float z0 = q0a[mt * 2 + half] + fpb3[0];
                            float z1 = q1a[mt * 2 + half] + fpb3[1];
                            #pragma unroll
                            for (int nw = 1; nw < 4; nw++) {
                                z0 += fpart[rl * 8 + nw * 2];
                                z1 += fpart[rl * 8 + nw * 2 + 1];
                            }
                            float nrm = fmaxf(sqrtf(z0 * z0 + z1 * z1), 1e-12f);
                            z0 /= nrm; z1 /= nrm;
                            float mm = fmaxf(z0, z1);
                            float lse = mm + logf(expf(z0 - mm) + expf(z1 - mm));
                            outF[2 * gr]     = z0 - lse;
                            outF[2 * gr + 1] = z1 - lse;
                        }
                    }
                }
            }
        } else if (epimode == 1) {
            int rbase = row0 + mrow0 + (lane >> 2);
            #pragma unroll
            for (int mt = 0; mt < 2; mt++) {
                #pragma unroll
                for (int half = 0; half < 2; half++) {
                    int gr = rbase + mt * 16 + half * 8;
                    if (gr >= M) continue;
                    #pragma unroll
                    for (int nt = 0; nt < 4; nt++) {
                        int col = cbase + nt * 8;
                        float o0 = fmaxf(acc[mt][nt][2 * half] + bias[col], 0.f);
                        float o1 = fmaxf(acc[mt][nt][2 * half + 1] + bias[col + 1], 0.f);
                        uint32_t hp, lp;
                        split2(o0, o1, hp, lp);
                        *(uint32_t*)(OutHi + (size_t)gr * D + col) = hp;
                        *(uint32_t*)(OutLo + (size_t)gr * D + col) = lp;
                    }
                }
            }
        } else {
            int rbase = row0 + mrow0 + (lane >> 2);
            #pragma unroll
            for (int mt = 0; mt < 2; mt++) {
                #pragma unroll
                for (int half = 0; half < 2; half++) {
                    int gr = rbase + mt * 16 + half * 8;
                    if (gr >= M) continue;
                    float* cp = Cf + (size_t)gr * D;
                    #pragma unroll
                    for (int nt = 0; nt < 4; nt++) {
                        int col = cbase + nt * 8;
                        float o0 = acc[mt][nt][2 * half];
                        float o1 = acc[mt][nt][2 * half + 1];
                        if (bias) { o0 += bias[col]; o1 += bias[col + 1]; }
                        if (relu) { o0 = fmaxf(o0, 0.f); o1 = fmaxf(o1, 0.f); }
                        *(float2*)(cp + col) = make_float2(o0, o1);
                    }
                }
            }
        }
        __syncthreads();
    }
}

// ---------------- aggregation: warp-per-dst; outmode 0 = bf16 hi/lo, 1 = fp32 ----
__global__ void agg_kernel(const float* __restrict__ H, const int* __restrict__ rowptr,
                           const int* __restrict__ eidx, const float* __restrict__ bias,
                           __nv_bfloat16* __restrict__ OutHi, __nv_bfloat16* __restrict__ OutLo,
                           float* __restrict__ OutF,
                           int relu, int outmode, int N) {
    int gw = (blockIdx.x * blockDim.x + threadIdx.x) >> 5;
    int lane = threadIdx.x & 31;
    if (gw >= N) return;
    int beg = rowptr[gw], end = rowptr[gw + 1];
    float4 acc = make_float4(0.f, 0.f, 0.f, 0.f);
    for (int j0 = beg; j0 < end; j0 += 32) {
        int cnt = min(32, end - j0);
        int e = (lane < cnt) ? eidx[j0 + lane] : 0;
        for (int t = 0; t < cnt; t++) {
            int s = __shfl_sync(0xFFFFFFFFu, e, t);
            float4 v = *(const float4*)(H + (size_t)s * D + (lane << 2));
            acc.x += v.x; acc.y += v.y; acc.z += v.z; acc.w += v.w;
        }
    }
    float4 bv = *(const float4*)(bias + (lane << 2));
    acc.x += bv.x; acc.y += bv.y; acc.z += bv.z; acc.w += bv.w;
    if (relu) {
        acc.x = fmaxf(acc.x, 0.f); acc.y = fmaxf(acc.y, 0.f);
        acc.z = fmaxf(acc.z, 0.f); acc.w = fmaxf(acc.w, 0.f);
    }
    if (outmode == 0) {
        uint2 hp, lp;
        split2(acc.x, acc.y, hp.x, lp.x);
        split2(acc.z, acc.w, hp.y, lp.y);
        *(uint2*)(OutHi + (size_t)gw * D + (lane << 2)) = hp;
        *(uint2*)(OutLo + (size_t)gw * D + (lane << 2)) = lp;
    } else {
        *(float4*)(OutF + (size_t)gw * D + (lane << 2)) = acc;
    }
}

// ---------------- launch ----------------
extern "C" void kernel_launch(void* const* d_in, const int* in_sizes, int n_in,
                              void* d_out, int out_size) {
    const float* x    = (const float*)d_in[0];
    const int*   adj  = (const int*)d_in[1];
    const int*   tedg = (const int*)d_in[2];
    const float* W1 = (const float*)d_in[3];  const float* b1  = (const float*)d_in[4];
    const float* W2 = (const float*)d_in[5];  const float* b2  = (const float*)d_in[6];
    const float* W3 = (const float*)d_in[7];  const float* b3  = (const float*)d_in[8];
    const float* P1 = (const float*)d_in[9];  const float* pb1 = (const float*)d_in[10];
    const float* P2 = (const float*)d_in[11]; const float* pb2 = (const float*)d_in[12];
    const float* P3 = (const float*)d_in[13]; const float* pb3 = (const float*)d_in[14];
    float* out = (float*)d_out;

    int N  = in_sizes[0] / D;
    int E  = in_sizes[1] / 2;
    int NE = in_sizes[2] / 2;

    cudaFuncSetAttribute((const void*)gemm_mma_kernel,
                         cudaFuncAttributeMaxDynamicSharedMemorySize, SMEM_BYTES);

    __nv_bfloat16 *Ahi, *Alo, *Whi, *Wlo;
    float *Hf, *emb;
    int *deg, *rowptr, *cur, *eidx, *bsum;
    cudaGetSymbolAddress((void**)&Ahi, g_Ahi);
    cudaGetSymbolAddress((void**)&Alo, g_Alo);
    cudaGetSymbolAddress((void**)&Hf,  g_Hf);
    cudaGetSymbolAddress((void**)&emb, g_emb);
    cudaGetSymbolAddress((void**)&deg,    g_deg);
    cudaGetSymbolAddress((void**)&rowptr, g_rowptr);
    cudaGetSymbolAddress((void**)&cur,    g_cur);
    cudaGetSymbolAddress((void**)&eidx,   g_eidx);
    cudaGetSymbolAddress((void**)&bsum,   g_bsum);
    cudaGetSymbolAddress((void**)&Whi,  g_Whi);
    cudaGetSymbolAddress((void**)&Wlo,  g_Wlo);

    const int* src = adj;
    const int* dst = adj + E;

    int nScanBlk = (N + 1023) / 1024;
    int tilesN  = (N + TM - 1) / TM;
    int tilesNE = (NE + TM - 1) / TM;
    int gN  = tilesN  < 296 ? tilesN  : 296;
    int gNE = tilesNE < 296 ? tilesNE : 296;
    int aggBlk = (N * 32 + 255) / 256;

    // ---- prep + L1 GEMM early, CSR chain after ----
    prep_weights_kernel<<<(5 * 16384 + 255) / 256, 256>>>(W1, W2, W3, P1, P2, Whi, Wlo);
    xsplit_kernel<<<2048, 256>>>(x, Ahi, Alo, N);
    zero_int_kernel<<<(N + 255) / 256, 256>>>(deg, N);
    gemm_mma_kernel<<<gN, 256, SMEM_BYTES>>>(Ahi, Alo, nullptr, nullptr, Whi, Wlo,
        nullptr, Hf, nullptr, nullptr, nullptr, nullptr, nullptr, N, 0, tilesN, 0, 0);
    hist_kernel<<<(E + 255) / 256, 256>>>(dst, E, deg);
    scan1_kernel<<<nScanBlk, 1024>>>(deg, rowptr, bsum, N);
    scan2_kernel<<<1, 32>>>(bsum, nScanBlk);
    scan3_kernel<<<nScanBlk, 1024>>>(deg, rowptr, cur, bsum, N);
    fill_csr_kernel<<<(E + 255) / 256, 256>>>(src, dst, E, cur, eidx);

    // ---- trunk ----
    agg_kernel<<<aggBlk, 256>>>(Hf, rowptr, eidx, b1, Ahi, Alo, nullptr, 1, 0, N);
    gemm_mma_kernel<<<gN, 256, SMEM_BYTES>>>(Ahi, Alo, nullptr, nullptr, Whi + 16384, Wlo + 16384,
        nullptr, Hf, nullptr, nullptr, nullptr, nullptr, nullptr, N, 0, tilesN, 0, 0);
    agg_kernel<<<aggBlk, 256>>>(Hf, rowptr, eidx, b2, Ahi, Alo, nullptr, 1, 0, N);
    gemm_mma_kernel<<<gN, 256, SMEM_BYTES>>>(Ahi, Alo, nullptr, nullptr, Whi + 2 * 16384, Wlo + 2 * 16384,
        nullptr, Hf, nullptr, nullptr, nullptr, nullptr, nullptr, N, 0, tilesN, 0, 0);
    agg_kernel<<<aggBlk, 256>>>(Hf, rowptr, eidx, b3, nullptr, nullptr, emb, 0, 1, N);

    // ---- link predictor ----
    gemm_mma_kernel<<<gNE, 256, SMEM_BYTES>>>(nullptr, nullptr, emb, tedg, Whi + 3 * 16384, Wlo + 3 * 16384,
        pb1, nullptr, Ahi, Alo, nullptr, nullptr, nullptr, NE, 1, tilesNE, 1, 1);
    gemm_mma_kernel<<<gNE, 256, SMEM_BYTES>>>(Ahi, Alo, nullptr, nullptr, Whi + 4 * 16384, Wlo + 4 * 16384,
        pb2, nullptr, nullptr, nullptr, P3, pb3, out, NE, 1, tilesNE, 0, 2);
}

// round 10
// speedup vs baseline: 1.1022x; 1.0505x over previous
#include <cuda_runtime.h>
#include <cuda_bf16.h>
#include <cuda_fp16.h>
#include <math.h>
#include <stdint.h>

// ---------------- problem constants ----------------
#define MAXN 50000
#define MAXE 800000
#define MAXNE 100000
#define D 128

// ---------------- device scratch ----------------
// 16-bit staging buffers. Trunk phase: g_Ahi holds fp16 A (single). Link phase:
// g_Ahi/g_Alo hold bf16 hi/lo. Same storage, different interpretation.
__device__ __nv_bfloat16 g_Ahi[(size_t)(MAXNE + 128) * D];
__device__ __nv_bfloat16 g_Alo[(size_t)(MAXNE + 128) * D];
__device__ float g_Hf [(size_t)MAXN * D];
__device__ float g_emb[(size_t)MAXN * D];
__device__ int   g_deg[MAXN];
__device__ int   g_rowptr[MAXN + 1];
__device__ int   g_cur[MAXN];
__device__ int   g_eidx[MAXE];
__device__ int   g_bsum[256];
// weights: slots 0..2 = W1..W3 as fp16 hi/lo; slots 3..4 = P1,P2 as bf16 hi/lo
__device__ __nv_bfloat16 g_Whi[5 * 16384];
__device__ __nv_bfloat16 g_Wlo[5 * 16384];

// ---------------- PTX helpers ----------------
__device__ __forceinline__ uint32_t smem_u32(const void* p) {
    uint32_t a;
    asm("{ .reg .u64 t; cvta.to.shared.u64 t, %1; cvt.u32.u64 %0, t; }" : "=r"(a) : "l"(p));
    return a;
}
__device__ __forceinline__ void ldsm4(uint32_t* r, uint32_t addr) {
    asm volatile("ldmatrix.sync.aligned.m8n8.x4.shared.b16 {%0,%1,%2,%3}, [%4];"
        : "=r"(r[0]), "=r"(r[1]), "=r"(r[2]), "=r"(r[3]) : "r"(addr));
}
__device__ __forceinline__ void mma_bf16(float* c, const uint32_t* a, const uint32_t* b) {
    asm volatile(
        "mma.sync.aligned.m16n8k16.row.col.f32.bf16.bf16.f32 "
        "{%0,%1,%2,%3}, {%4,%5,%6,%7}, {%8,%9}, {%0,%1,%2,%3};"
        : "+f"(c[0]), "+f"(c[1]), "+f"(c[2]), "+f"(c[3])
        : "r"(a[0]), "r"(a[1]), "r"(a[2]), "r"(a[3]), "r"(b[0]), "r"(b[1]));
}
__device__ __forceinline__ void mma_f16(float* c, const uint32_t* a, const uint32_t* b) {
    asm volatile(
        "mma.sync.aligned.m16n8k16.row.col.f32.f16.f16.f32 "
        "{%0,%1,%2,%3}, {%4,%5,%6,%7}, {%8,%9}, {%0,%1,%2,%3};"
        : "+f"(c[0]), "+f"(c[1]), "+f"(c[2]), "+f"(c[3])
        : "r"(a[0]), "r"(a[1]), "r"(a[2]), "r"(a[3]), "r"(b[0]), "r"(b[1]));
}
__device__ __forceinline__ void cp_async16(uint32_t saddr, const void* gptr) {
    asm volatile("cp.async.cg.shared.global [%0], [%1], 16;" :: "r"(saddr), "l"(gptr));
}
#define CP_COMMIT() asm volatile("cp.async.commit_group;" ::: "memory")
template <int NN> __device__ __forceinline__ void cp_wait() {
    asm volatile("cp.async.wait_group %0;" :: "n"(NN) : "memory");
}
__device__ __forceinline__ void split2b(float a, float b, uint32_t& hi, uint32_t& lo) {
    __nv_bfloat162 h = __floats2bfloat162_rn(a, b);
    float ra = a - __bfloat162float(h.x);
    float rb = b - __bfloat162float(h.y);
    __nv_bfloat162 l = __floats2bfloat162_rn(ra, rb);
    hi = *(uint32_t*)&h;
    lo = *(uint32_t*)&l;
}

// ---------------- CSR build kernels ----------------
__global__ void zero_int_kernel(int* p, int n) {
    for (int i = blockIdx.x * blockDim.x + threadIdx.x; i < n; i += gridDim.x * blockDim.x)
        p[i] = 0;
}
__global__ void hist_kernel(const int* __restrict__ dst, int E, int* __restrict__ deg) {
    for (int e = blockIdx.x * blockDim.x + threadIdx.x; e < E; e += gridDim.x * blockDim.x)
        atomicAdd(&deg[dst[e]], 1);
}
__global__ void scan1_kernel(const int* __restrict__ deg, int* __restrict__ rowptr,
                             int* __restrict__ bsum, int n) {
    __shared__ int wsum[32];
    int tid = threadIdx.x, lane = tid & 31, w = tid >> 5;
    int i = blockIdx.x * 1024 + tid;
    int v = (i < n) ? deg[i] : 0;
    int s = v;
    #pragma unroll
    for (int off = 1; off < 32; off <<= 1) {
        int t = __shfl_up_sync(0xFFFFFFFFu, s, off);
        if (lane >= off) s += t;
    }
    if (lane == 31) wsum[w] = s;
    __syncthreads();
    if (w == 0) {
        int ws = wsum[lane];
        #pragma unroll
        for (int off = 1; off < 32; off <<= 1) {
            int t = __shfl_up_sync(0xFFFFFFFFu, ws, off);
            if (lane >= off) ws += t;
        }
        wsum[lane] = ws;
    }
    __syncthreads();
    int prev = (w > 0) ? wsum[w - 1] : 0;
    int incl = prev + s;
    if (i < n) rowptr[i] = incl - v;
    if (tid == 1023) bsum[blockIdx.x] = incl;
}
__global__ void scan2_kernel(int* bsum, int nb) {
    int lane = threadIdx.x;
    int carry = 0;
    for (int base = 0; base < nb; base += 32) {
        int i = base + lane;
        int v = (i < nb) ? bsum[i] : 0;
        int s = v;
        #pragma unroll
        for (int off = 1; off < 32; off <<= 1) {
            int t = __shfl_up_sync(0xFFFFFFFFu, s, off);
            if (lane >= off) s += t;
        }
        if (i < nb) bsum[i] = carry + s - v;
        carry += __shfl_sync(0xFFFFFFFFu, s, 31);
    }
}
__global__ void scan3_kernel(const int* __restrict__ deg, int* __restrict__ rowptr,
                             int* __restrict__ cur, const int* __restrict__ bsum, int n) {
    int i = blockIdx.x * 1024 + threadIdx.x;
    if (i >= n) return;
    int val = rowptr[i] + bsum[blockIdx.x];
    rowptr[i] = val;
    cur[i] = val;
    if (i == n - 1) rowptr[n] = val + deg[n - 1];
}
__global__ void fill_csr_kernel(const int* __restrict__ src, const int* __restrict__ dst,
                                int E, int* __restrict__ cur, int* __restrict__ eidx) {
    for (int e = blockIdx.x * blockDim.x + threadIdx.x; e < E; e += gridDim.x * blockDim.x) {
        int d = dst[e];
        int p = atomicAdd(&cur[d], 1);
        eidx[p] = src[e];
    }
}

// ---------------- prep kernels ----------------
// W1..W3 -> fp16 hi/lo; P1,P2 -> bf16 hi/lo. All transposed [n][k].
__global__ void prep_weights_kernel(const float* W1, const float* W2, const float* W3,
                                    const float* P1, const float* P2,
                                    __nv_bfloat16* hi, __nv_bfloat16* lo) {
    int idx = blockIdx.x * blockDim.x + threadIdx.x;
    if (idx >= 5 * 16384) return;
    int w = idx >> 14;
    int t = idx & 16383;
    int n = t >> 7;
    int k = t & 127;
    const float* Ws = (w == 0) ? W1 : (w == 1) ? W2 : (w == 2) ? W3 : (w == 3) ? P1 : P2;
    float v = Ws[(k << 7) | n];
    if (w < 3) {
        __half h = __float2half_rn(v);
        float rem = v - __half2float(h);
        ((__half*)hi)[idx] = h;
        ((__half*)lo)[idx] = __float2half_rn(rem);
    } else {
        __nv_bfloat16 h = __float2bfloat16(v);
        float rem = v - __bfloat162float(h);
        hi[idx] = h;
        lo[idx] = __float2bfloat16(rem);
    }
}
// x fp32 -> fp16 (single buffer)
__global__ void xhalf_kernel(const float* __restrict__ x, __half* __restrict__ Ah, int N) {
    int n4 = N * 32;
    for (int idx = blockIdx.x * blockDim.x + threadIdx.x; idx < n4; idx += gridDim.x * blockDim.x) {
        float4 v = ((const float4*)x)[idx];
        __half2 h01 = __floats2half2_rn(v.x, v.y);
        __half2 h23 = __floats2half2_rn(v.z, v.w);
        uint2 p;
        p.x = *(uint32_t*)&h01; p.y = *(uint32_t*)&h23;
        *(uint2*)(Ah + (size_t)idx * 4) = p;
    }
}

// ================= fp16 2-pass GEMM (trunk): C = A @ (Wh + Wl), fp32 out =================
#define ASTRIDE 136
#define TM 64
#define ABUF (TM * ASTRIDE)                // per-A-array elems
#define WBUF (128 * ASTRIDE)
// fp16 layout: A single + Wh + Wl
#define H_SA 0
#define H_SWH ABUF
#define H_SWL (ABUF + WBUF)
#define H_ELEMS (ABUF + 2 * WBUF)          // 43520 fp16 = 87040 B
#define H_SMEM_BYTES (H_ELEMS * 2 + 64)

__global__ void __launch_bounds__(256, 2)
gemm_f16_kernel(const __half* __restrict__ A,
                const __half* __restrict__ Wt_hi, const __half* __restrict__ Wt_lo,
                float* __restrict__ Cf, int M, int numTiles) {
    extern __shared__ __half smh[];
    uint32_t sbase = smem_u32(smh);
    int tid = threadIdx.x, wid = tid >> 5, lane = tid & 31;

    // stage W hi/lo (once per CTA)
    {
        const uint4* wh = (const uint4*)Wt_hi;
        const uint4* wl = (const uint4*)Wt_lo;
        for (int i = tid; i < 2048; i += 256) {
            int r = i >> 4, c = i & 15;
            *(uint4*)(smh + H_SWH + r * ASTRIDE + c * 8) = wh[i];
            *(uint4*)(smh + H_SWL + r * ASTRIDE + c * 8) = wl[i];
        }
    }

    int mwid = wid >> 2;
    int nwid = wid & 3;
    int mrow0 = mwid << 5;
    int ncol0 = nwid << 5;

    uint32_t aRel = (uint32_t)(mrow0 + (lane & 15)) * (ASTRIDE * 2)
                  + (uint32_t)(((lane >> 4) << 3) * 2);
    uint32_t a0 = sbase + (H_SA * 2) + aRel;
    uint32_t a1 = a0 + 16 * (ASTRIDE * 2);

    uint32_t bN = (uint32_t)(ncol0 + ((lane >> 4) << 3) + (lane & 7));
    uint32_t bKB = (uint32_t)((((lane >> 3) & 1) << 3) * 2);
    uint32_t bHiBase = sbase + (H_SWH * 2) + bN * (ASTRIDE * 2) + bKB;
    uint32_t bLoBase = bHiBase + WBUF * 2;

    for (int t = blockIdx.x; t < numTiles; t += gridDim.x) {
        int row0 = t * TM;
        // stage A (64 x 128 fp16) via cp.async
        #pragma unroll
        for (int it = 0; it < 4; it++) {
            int idx = it * 256 + tid;              // 0..1023
            int r = idx >> 4, c = idx & 15;
            size_t goff = (size_t)(row0 + r) * D + c * 8;
            uint32_t soff = (r * ASTRIDE + c * 8) * 2;
            cp_async16(sbase + (H_SA * 2) + soff, A + goff);
        }
        CP_COMMIT();
        cp_wait<0>();
        __syncthreads();

        float acc[2][4][4];
        #pragma unroll
        for (int mt = 0; mt < 2; mt++)
            #pragma unroll
            for (int nt = 0; nt < 4; nt++)
                #pragma unroll
                for (int q = 0; q < 4; q++) acc[mt][nt][q] = 0.0f;

        #pragma unroll
        for (int ks = 0; ks < 8; ks++) {
            uint32_t koffB = (uint32_t)(ks * 32);
            uint32_t af[2][4];
            ldsm4(af[0], a0 + koffB);
            ldsm4(af[1], a1 + koffB);
            uint32_t bh[4][2], bl[4][2];
            #pragma unroll
            for (int np = 0; np < 2; np++) {
                uint32_t r4[4];
                ldsm4(r4, bHiBase + (uint32_t)(np * 16 * ASTRIDE * 2) + koffB);
                bh[2 * np][0] = r4[0]; bh[2 * np][1] = r4[1];
                bh[2 * np + 1][0] = r4[2]; bh[2 * np + 1][1] = r4[3];
                ldsm4(r4, bLoBase + (uint32_t)(np * 16 * ASTRIDE * 2) + koffB);
                bl[2 * np][0] = r4[0]; bl[2 * np][1] = r4[1];
                bl[2 * np + 1][0] = r4[2]; bl[2 * np + 1][1] = r4[3];
            }
            #pragma unroll
            for (int mt = 0; mt < 2; mt++)
                #pragma unroll
                for (int nt = 0; nt < 4; nt++) {
                    mma_f16(acc[mt][nt], af[mt], bh[nt]);
                    mma_f16(acc[mt][nt], af[mt], bl[nt]);
                }
        }

        int cbase = ncol0 + ((lane & 3) << 1);
        int rbase = row0 + mrow0 + (lane >> 2);
        #pragma unroll
        for (int mt = 0; mt < 2; mt++) {
            #pragma unroll
            for (int half = 0; half < 2; half++) {
                int gr = rbase + mt * 16 + half * 8;
                if (gr >= M) continue;
                float* cp = Cf + (size_t)gr * D;
                #pragma unroll
                for (int nt = 0; nt < 4; nt++) {
                    int col = cbase + nt * 8;
                    *(float2*)(cp + col) = make_float2(acc[mt][nt][2 * half],
                                                       acc[mt][nt][2 * half + 1]);
                }
            }
        }
        __syncthreads();
    }
}

// ================= bf16 3-pass GEMM (link predictor) =================
#define B_SAHI 0
#define B_SALO ABUF
#define B_SWH (2 * ABUF)
#define B_SWL (2 * ABUF + WBUF)
#define B_ELEMS (2 * ABUF + 2 * WBUF)
#define B_SMEM_BYTES (B_ELEMS * 2 + (512 + 256 + 8) * 4)

// stagemode: 0 = cp.async bf16 hi/lo; 1 = ALU gather products (embf, tedg)
// epimode:   1 = bf16 hi/lo out (+bias+relu); 2 = fused final
__global__ void __launch_bounds__(256, 2)
gemm_bf16_kernel(const __nv_bfloat16* __restrict__ Ahi, const __nv_bfloat16* __restrict__ Alo,
                 const float* __restrict__ embf, const int* __restrict__ tedg,
                 const __nv_bfloat16* __restrict__ Wt_hi, const __nv_bfloat16* __restrict__ Wt_lo,
                 const float* __restrict__ bias,
                 __nv_bfloat16* __restrict__ OutHi, __nv_bfloat16* __restrict__ OutLo,
                 const float* __restrict__ P3, const float* __restrict__ pb3,
                 float* __restrict__ outF,
                 int M, int numTiles, int stagemode, int epimode) {
    extern __shared__ __nv_bfloat16 sm[];
    uint32_t sbase = smem_u32(sm);
    float* fpart = (float*)(sm + B_ELEMS);
    float* fP3 = fpart + 512;
    float* fpb3 = fP3 + 256;
    int tid = threadIdx.x, wid = tid >> 5, lane = tid & 31;

    {
        const uint4* wh = (const uint4*)Wt_hi;
        const uint4* wl = (const uint4*)Wt_lo;
        for (int i = tid; i < 2048; i += 256) {
            int r = i >> 4, c = i & 15;
            *(uint4*)(sm + B_SWH + r * ASTRIDE + c * 8) = wh[i];
            *(uint4*)(sm + B_SWL + r * ASTRIDE + c * 8) = wl[i];
        }
        if (epimode == 2) {
            fP3[tid] = P3[tid];
            if (tid < 2) fpb3[tid] = pb3[tid];
        }
    }

    int mwid = wid >> 2;
    int nwid = wid & 3;
    int mrow0 = mwid << 5;
    int ncol0 = nwid << 5;

    uint32_t aRel = (uint32_t)(mrow0 + (lane & 15)) * (ASTRIDE * 2)
                  + (uint32_t)(((lane >> 4) << 3) * 2);
    uint32_t aHi0 = sbase + (B_SAHI * 2) + aRel;
    uint32_t aHi1 = aHi0 + 16 * (ASTRIDE * 2);
    uint32_t aLo0 = aHi0 + ABUF * 2;
    uint32_t aLo1 = aHi1 + ABUF * 2;

    uint32_t bN = (uint32_t)(ncol0 + ((lane >> 4) << 3) + (lane & 7));
    uint32_t bKB = (uint32_t)((((lane >> 3) & 1) << 3) * 2);
    uint32_t bHiBase = sbase + (B_SWH * 2) + bN * (ASTRIDE * 2) + bKB;
    uint32_t bLoBase = bHiBase + WBUF * 2;

    for (int t = blockIdx.x; t < numTiles; t += gridDim.x) {
        int row0 = t * TM;

        if (stagemode == 0) {
            #pragma unroll
            for (int it = 0; it < 4; it++) {
                int idx = it * 256 + tid;
                int r = idx >> 4, c = idx & 15;
                size_t goff = (size_t)(row0 + r) * D + c * 8;
                uint32_t soff = (r * ASTRIDE + c * 8) * 2;
                cp_async16(sbase + (B_SAHI * 2) + soff, Ahi + goff);
                cp_async16(sbase + (B_SALO * 2) + soff, Alo + goff);
            }
            CP_COMMIT();
            cp_wait<0>();
        } else {
            #pragma unroll
            for (int it = 0; it < 8; it++) {
                int idx = it * 256 + tid;
                int r = idx >> 5;
                int c4 = idx & 31;
                int grow = row0 + r;
                float4 v;
                if (grow < M) {
                    int s = tedg[2 * grow];
                    int d = tedg[2 * grow + 1];
                    float4 a = *(const float4*)(embf + (size_t)s * D + c4 * 4);
                    float4 b = *(const float4*)(embf + (size_t)d * D + c4 * 4);
                    v = make_float4(a.x * b.x, a.y * b.y, a.z * b.z, a.w * b.w);
                } else {
                    v = make_float4(0.f, 0.f, 0.f, 0.f);
                }
                uint2 hp, lp;
                split2b(v.x, v.y, hp.x, lp.x);
                split2b(v.z, v.w, hp.y, lp.y);
                *(uint2*)(sm + B_SAHI + r * ASTRIDE + c4 * 4) = hp;
                *(uint2*)(sm + B_SALO + r * ASTRIDE + c4 * 4) = lp;
            }
        }
        __syncthreads();

        float acc[2][4][4];
        #pragma unroll
        for (int mt = 0; mt < 2; mt++)
            #pragma unroll
            for (int nt = 0; nt < 4; nt++)
                #pragma unroll
                for (int q = 0; q < 4; q++) acc[mt][nt][q] = 0.0f;

        #pragma unroll
        for (int ks = 0; ks < 8; ks++) {
            uint32_t koffB = (uint32_t)(ks * 32);
            uint32_t ah[2][4], al[2][4];
            ldsm4(ah[0], aHi0 + koffB);
            ldsm4(ah[1], aHi1 + koffB);
            ldsm4(al[0], aLo0 + koffB);
            ldsm4(al[1], aLo1 + koffB);
            uint32_t bh[4][2], bl[4][2];
            #pragma unroll
            for (int np = 0; np < 2; np++) {
                uint32_t r4[4];
                ldsm4(r4, bHiBase + (uint32_t)(np * 16 * ASTRIDE * 2) + koffB);
                bh[2 * np][0] = r4[0]; bh[2 * np][1] = r4[1];
                bh[2 * np + 1][0] = r4[2]; bh[2 * np + 1][1] = r4[3];
                ldsm4(r4, bLoBase + (uint32_t)(np * 16 * ASTRIDE * 2) + koffB);
                bl[2 * np][0] = r4[0]; bl[2 * np][1] = r4[1];
                bl[2 * np + 1][0] = r4[2]; bl[2 * np + 1][1] = r4[3];
            }
            #pragma unroll
            for (int mt = 0; mt < 2; mt++)
                #pragma unroll
                for (int nt = 0; nt < 4; nt++) {
                    mma_bf16(acc[mt][nt], ah[mt], bh[nt]);
                    mma_bf16(acc[mt][nt], ah[mt], bl[nt]);
                    mma_bf16(acc[mt][nt], al[mt], bh[nt]);
                }
        }

        int cbase = ncol0 + ((lane & 3) << 1);

        if (epimode == 2) {
            float q0a[4], q1a[4];
            #pragma unroll
            for (int mt = 0; mt < 2; mt++) {
                #pragma unroll
                for (int half = 0; half < 2; half++) {
                    float q0 = 0.f, q1 = 0.f;
                    #pragma unroll
                    for (int nt = 0; nt < 4; nt++) {
                        int col = cbase + nt * 8;
                        float z0 = fmaxf(acc[mt][nt][2 * half] + bias[col], 0.f);
                        float z1 = fmaxf(acc[mt][nt][2 * half + 1] + bias[col + 1], 0.f);
                        q0 += z0 * fP3[2 * col] + z1 * fP3[2 * (col + 1)];
                        q1 += z0 * fP3[2 * col + 1] + z1 * fP3[2 * (col + 1) + 1];
                    }
                    q0 += __shfl_xor_sync(0xFFFFFFFFu, q0, 1);
                    q0 += __shfl_xor_sync(0xFFFFFFFFu, q0, 2);
                    q1 += __shfl_xor_sync(0xFFFFFFFFu, q1, 1);
                    q1 += __shfl_xor_sync(0xFFFFFFFFu, q1, 2);
                    q0a[mt * 2 + half] = q0;
                    q1a[mt * 2 + half] = q1;
                    if (nwid != 0 && (lane & 3) == 0) {
                        int rl = mrow0 + mt * 16 + half * 8 + (lane >> 2);
                        fpart[rl * 8 + nwid * 2]     = q0;
                        fpart[rl * 8 + nwid * 2 + 1] = q1;
                    }
                }
            }
            __syncthreads();
            if (nwid == 0 && (lane & 3) == 0) {
                #pragma unroll
                for (int mt = 0; mt < 2; mt++) {
                    #pragma unroll
                    for (int half = 0; half < 2; half++) {
                        int rl = mrow0 + mt * 16 + half * 8 + (lane >> 2);
                        int gr = row0 + rl;
                        if (gr < M) {
                            float z0 = q0a[mt * 2 + half] + fpb3[0];
                            float z1 = q1a[mt * 2 + half] + fpb3[1];
                            #pragma unroll
                            for (int nw = 1; nw < 4; nw++) {
                                z0 += fpart[rl * 8 + nw * 2];
                                z1 += fpart[rl * 8 + nw * 2 + 1];
                            }
                            float nrm = fmaxf(sqrtf(z0 * z0 + z1 * z1), 1e-12f);
                            z0 /= nrm; z1 /= nrm;
                            float mm = fmaxf(z0, z1);
                            float lse = mm + logf(expf(z0 - mm) + expf(z1 - mm));
                            outF[2 * gr]     = z0 - lse;
                            outF[2 * gr + 1] = z1 - lse;
                        }
                    }
                }
            }
        } else {
            int rbase = row0 + mrow0 + (lane >> 2);
            #pragma unroll
            for (int mt = 0; mt < 2; mt++) {
                #pragma unroll
                for (int half = 0; half < 2; half++) {
                    int gr = rbase + mt * 16 + half * 8;
                    if (gr >= M) continue;
                    #pragma unroll
                    for (int nt = 0; nt < 4; nt++) {
                        int col = cbase + nt * 8;
                        float o0 = fmaxf(acc[mt][nt][2 * half] + bias[col], 0.f);
                        float o1 = fmaxf(acc[mt][nt][2 * half + 1] + bias[col + 1], 0.f);
                        uint32_t hp, lp;
                        split2b(o0, o1, hp, lp);
                        *(uint32_t*)(OutHi + (size_t)gr * D + col) = hp;
                        *(uint32_t*)(OutLo + (size_t)gr * D + col) = lp;
                    }
                }
            }
        }
        __syncthreads();
    }
}

// ---------------- aggregation: warp-per-dst; outmode 0 = fp16 single, 1 = fp32 ----
__global__ void agg_kernel(const float* __restrict__ H, const int* __restrict__ rowptr,
                           const int* __restrict__ eidx, const float* __restrict__ bias,
                           __half* __restrict__ OutH, float* __restrict__ OutF,
                           int relu, int outmode, int N) {
    int gw = (blockIdx.x * blockDim.x + threadIdx.x) >> 5;
    int lane = threadIdx.x & 31;
    if (gw >= N) return;
    int beg = rowptr[gw], end = rowptr[gw + 1];
    float4 acc = make_float4(0.f, 0.f, 0.f, 0.f);
    for (int j0 = beg; j0 < end; j0 += 32) {
        int cnt = min(32, end - j0);
        int e = (lane < cnt) ? eidx[j0 + lane] : 0;
        for (int t = 0; t < cnt; t++) {
            int s = __shfl_sync(0xFFFFFFFFu, e, t);
            float4 v = *(const float4*)(H + (size_t)s * D + (lane << 2));
            acc.x += v.x; acc.y += v.y; acc.z += v.z; acc.w += v.w;
        }
    }
    float4 bv = *(const float4*)(bias + (lane << 2));
    acc.x += bv.x; acc.y += bv.y; acc.z += bv.z; acc.w += bv.w;
    if (relu) {
        acc.x = fmaxf(acc.x, 0.f); acc.y = fmaxf(acc.y, 0.f);
        acc.z = fmaxf(acc.z, 0.f); acc.w = fmaxf(acc.w, 0.f);
    }
    if (outmode == 0) {
        __half2 h01 = __floats2half2_rn(acc.x, acc.y);
        __half2 h23 = __floats2half2_rn(acc.z, acc.w);
        uint2 p;
        p.x = *(uint32_t*)&h01; p.y = *(uint32_t*)&h23;
        *(uint2*)(OutH + (size_t)gw * D + (lane << 2)) = p;
    } else {
        *(float4*)(OutF + (size_t)gw * D + (lane << 2)) = acc;
    }
}

// ---------------- launch ----------------
extern "C" void kernel_launch(void* const* d_in, const int* in_sizes, int n_in,
                              void* d_out, int out_size) {
    const float* x    = (const float*)d_in[0];
    const int*   adj  = (const int*)d_in[1];
    const int*   tedg = (const int*)d_in[2];
    const float* W1 = (const float*)d_in[3];  const float* b1  = (const float*)d_in[4];
    const float* W2 = (const float*)d_in[5];  const float* b2  = (const float*)d_in[6];
    const float* W3 = (const float*)d_in[7];  const float* b3  = (const float*)d_in[8];
    const float* P1 = (const float*)d_in[9];  const float* pb1 = (const float*)d_in[10];
    const float* P2 = (const float*)d_in[11]; const float* pb2 = (const float*)d_in[12];
    const float* P3 = (const float*)d_in[13]; const float* pb3 = (const float*)d_in[14];
    float* out = (float*)d_out;

    int N  = in_sizes[0] / D;
    int E  = in_sizes[1] / 2;
    int NE = in_sizes[2] / 2;

    cudaFuncSetAttribute((const void*)gemm_f16_kernel,
                         cudaFuncAttributeMaxDynamicSharedMemorySize, H_SMEM_BYTES);
    cudaFuncSetAttribute((const void*)gemm_bf16_kernel,
                         cudaFuncAttributeMaxDynamicSharedMemorySize, B_SMEM_BYTES);

    __nv_bfloat16 *Ahi, *Alo, *Whi, *Wlo;
    float *Hf, *emb;
    int *deg, *rowptr, *cur, *eidx, *bsum;
    cudaGetSymbolAddress((void**)&Ahi, g_Ahi);
    cudaGetSymbolAddress((void**)&Alo, g_Alo);
    cudaGetSymbolAddress((void**)&Hf,  g_Hf);
    cudaGetSymbolAddress((void**)&emb, g_emb);
    cudaGetSymbolAddress((void**)&deg,    g_deg);
    cudaGetSymbolAddress((void**)&rowptr, g_rowptr);
    cudaGetSymbolAddress((void**)&cur,    g_cur);
    cudaGetSymbolAddress((void**)&eidx,   g_eidx);
    cudaGetSymbolAddress((void**)&bsum,   g_bsum);
    cudaGetSymbolAddress((void**)&Whi,  g_Whi);
    cudaGetSymbolAddress((void**)&Wlo,  g_Wlo);

    __half* Ah16 = (__half*)Ahi;                       // trunk A (fp16 single)
    const __half* Wh16 = (const __half*)Whi;           // slots 0..2
    const __half* Wl16 = (const __half*)Wlo;

    const int* src = adj;
    const int* dst = adj + E;

    int nScanBlk = (N + 1023) / 1024;
    int tilesN  = (N + TM - 1) / TM;
    int tilesNE = (NE + TM - 1) / TM;
    int gN  = tilesN  < 296 ? tilesN  : 296;
    int gNE = tilesNE < 296 ? tilesNE : 296;
    int aggBlk = (N * 32 + 255) / 256;

    // ---- prep + L1 GEMM early, CSR chain after (single stream, graph-linear) ----
    prep_weights_kernel<<<(5 * 16384 + 255) / 256, 256>>>(W1, W2, W3, P1, P2, Whi, Wlo);
    xhalf_kernel<<<2048, 256>>>(x, Ah16, N);
    zero_int_kernel<<<(N + 255) / 256, 256>>>(deg, N);
    gemm_f16_kernel<<<gN, 256, H_SMEM_BYTES>>>(Ah16, Wh16, Wl16, Hf, N, tilesN);
    hist_kernel<<<(E + 255) / 256, 256>>>(dst, E, deg);
    scan1_kernel<<<nScanBlk, 1024>>>(deg, rowptr, bsum, N);
    scan2_kernel<<<1, 32>>>(bsum, nScanBlk);
    scan3_kernel<<<nScanBlk, 1024>>>(deg, rowptr, cur, bsum, N);
    fill_csr_kernel<<<(E + 255) / 256, 256>>>(src, dst, E, cur, eidx);

    // ---- trunk ----
    agg_kernel<<<aggBlk, 256>>>(Hf, rowptr, eidx, b1, Ah16, nullptr, 1, 0, N);
    gemm_f16_kernel<<<gN, 256, H_SMEM_BYTES>>>(Ah16, Wh16 + 16384, Wl16 + 16384, Hf, N, tilesN);
    agg_kernel<<<aggBlk, 256>>>(Hf, rowptr, eidx, b2, Ah16, nullptr, 1, 0, N);
    gemm_f16_kernel<<<gN, 256, H_SMEM_BYTES>>>(Ah16, Wh16 + 2 * 16384, Wl16 + 2 * 16384, Hf, N, tilesN);
    agg_kernel<<<aggBlk, 256>>>(Hf, rowptr, eidx, b3, nullptr, emb, 0, 1, N);

    // ---- link predictor (bf16 3-pass; values can exceed fp16 range) ----
    gemm_bf16_kernel<<<gNE, 256, B_SMEM_BYTES>>>(nullptr, nullptr, emb, tedg,
        Whi + 3 * 16384, Wlo + 3 * 16384, pb1, Ahi, Alo, nullptr, nullptr, nullptr,
        NE, tilesNE, 1, 1);
    gemm_bf16_kernel<<<gNE, 256, B_SMEM_BYTES>>>(Ahi, Alo, nullptr, nullptr,
        Whi + 4 * 16384, Wlo + 4 * 16384, pb2, nullptr, nullptr, P3, pb3, out,
        NE, tilesNE, 0, 2);
}

// round 11
// speedup vs baseline: 1.1583x; 1.0508x over previous
#include <cuda_runtime.h>
#include <cuda_bf16.h>
#include <cuda_fp16.h>
#include <math.h>
#include <stdint.h>

// ---------------- problem constants ----------------
#define MAXN 50000
#define MAXE 800000
#define MAXNE 100000
#define D 128

// ---------------- device scratch ----------------
__device__ __nv_bfloat16 g_Ahi[(size_t)(MAXNE + 128) * D];
__device__ __nv_bfloat16 g_Alo[(size_t)(MAXNE + 128) * D];
__device__ __half g_Hh [(size_t)(MAXN + 128) * D];   // fp16 trunk intermediate (GEMM out)
__device__ float g_emb[(size_t)MAXN * D];            // final embeddings (fp32)
__device__ int   g_deg[MAXN];
__device__ int   g_rowptr[MAXN + 1];
__device__ int   g_cur[MAXN];
__device__ int   g_eidx[MAXE];
__device__ int   g_bsum[256];
// weights: slots 0..2 = W1..W3 fp16 hi/lo; slots 3..4 = P1,P2 bf16 hi/lo
__device__ __nv_bfloat16 g_Whi[5 * 16384];
__device__ __nv_bfloat16 g_Wlo[5 * 16384];

// ---------------- PTX helpers ----------------
__device__ __forceinline__ uint32_t smem_u32(const void* p) {
    uint32_t a;
    asm("{ .reg .u64 t; cvta.to.shared.u64 t, %1; cvt.u32.u64 %0, t; }" : "=r"(a) : "l"(p));
    return a;
}
__device__ __forceinline__ void ldsm4(uint32_t* r, uint32_t addr) {
    asm volatile("ldmatrix.sync.aligned.m8n8.x4.shared.b16 {%0,%1,%2,%3}, [%4];"
        : "=r"(r[0]), "=r"(r[1]), "=r"(r[2]), "=r"(r[3]) : "r"(addr));
}
__device__ __forceinline__ void mma_bf16(float* c, const uint32_t* a, const uint32_t* b) {
    asm volatile(
        "mma.sync.aligned.m16n8k16.row.col.f32.bf16.bf16.f32 "
        "{%0,%1,%2,%3}, {%4,%5,%6,%7}, {%8,%9}, {%0,%1,%2,%3};"
        : "+f"(c[0]), "+f"(c[1]), "+f"(c[2]), "+f"(c[3])
        : "r"(a[0]), "r"(a[1]), "r"(a[2]), "r"(a[3]), "r"(b[0]), "r"(b[1]));
}
__device__ __forceinline__ void mma_f16(float* c, const uint32_t* a, const uint32_t* b) {
    asm volatile(
        "mma.sync.aligned.m16n8k16.row.col.f32.f16.f16.f32 "
        "{%0,%1,%2,%3}, {%4,%5,%6,%7}, {%8,%9}, {%0,%1,%2,%3};"
        : "+f"(c[0]), "+f"(c[1]), "+f"(c[2]), "+f"(c[3])
        : "r"(a[0]), "r"(a[1]), "r"(a[2]), "r"(a[3]), "r"(b[0]), "r"(b[1]));
}
__device__ __forceinline__ void cp_async16(uint32_t saddr, const void* gptr) {
    asm volatile("cp.async.cg.shared.global [%0], [%1], 16;" :: "r"(saddr), "l"(gptr));
}
#define CP_COMMIT() asm volatile("cp.async.commit_group;" ::: "memory")
template <int NN> __device__ __forceinline__ void cp_wait() {
    asm volatile("cp.async.wait_group %0;" :: "n"(NN) : "memory");
}
__device__ __forceinline__ void split2b(float a, float b, uint32_t& hi, uint32_t& lo) {
    __nv_bfloat162 h = __floats2bfloat162_rn(a, b);
    float ra = a - __bfloat162float(h.x);
    float rb = b - __bfloat162float(h.y);
    __nv_bfloat162 l = __floats2bfloat162_rn(ra, rb);
    hi = *(uint32_t*)&h;
    lo = *(uint32_t*)&l;
}

// ---------------- CSR build kernels ----------------
__global__ void zero_int_kernel(int* p, int n) {
    for (int i = blockIdx.x * blockDim.x + threadIdx.x; i < n; i += gridDim.x * blockDim.x)
        p[i] = 0;
}
__global__ void hist_kernel(const int* __restrict__ dst, int E, int* __restrict__ deg) {
    for (int e = blockIdx.x * blockDim.x + threadIdx.x; e < E; e += gridDim.x * blockDim.x)
        atomicAdd(&deg[dst[e]], 1);
}
__global__ void scan1_kernel(const int* __restrict__ deg, int* __restrict__ rowptr,
                             int* __restrict__ bsum, int n) {
    __shared__ int wsum[32];
    int tid = threadIdx.x, lane = tid & 31, w = tid >> 5;
    int i = blockIdx.x * 1024 + tid;
    int v = (i < n) ? deg[i] : 0;
    int s = v;
    #pragma unroll
    for (int off = 1; off < 32; off <<= 1) {
        int t = __shfl_up_sync(0xFFFFFFFFu, s, off);
        if (lane >= off) s += t;
    }
    if (lane == 31) wsum[w] = s;
    __syncthreads();
    if (w == 0) {
        int ws = wsum[lane];
        #pragma unroll
        for (int off = 1; off < 32; off <<= 1) {
            int t = __shfl_up_sync(0xFFFFFFFFu, ws, off);
            if (lane >= off) ws += t;
        }
        wsum[lane] = ws;
    }
    __syncthreads();
    int prev = (w > 0) ? wsum[w - 1] : 0;
    int incl = prev + s;
    if (i < n) rowptr[i] = incl - v;
    if (tid == 1023) bsum[blockIdx.x] = incl;
}
__global__ void scan2_kernel(int* bsum, int nb) {
    int lane = threadIdx.x;
    int carry = 0;
    for (int base = 0; base < nb; base += 32) {
        int i = base + lane;
        int v = (i < nb) ? bsum[i] : 0;
        int s = v;
        #pragma unroll
        for (int off = 1; off < 32; off <<= 1) {
            int t = __shfl_up_sync(0xFFFFFFFFu, s, off);
            if (lane >= off) s += t;
        }
        if (i < nb) bsum[i] = carry + s - v;
        carry += __shfl_sync(0xFFFFFFFFu, s, 31);
    }
}
__global__ void scan3_kernel(const int* __restrict__ deg, int* __restrict__ rowptr,
                             int* __restrict__ cur, const int* __restrict__ bsum, int n) {
    int i = blockIdx.x * 1024 + threadIdx.x;
    if (i >= n) return;
    int val = rowptr[i] + bsum[blockIdx.x];
    rowptr[i] = val;
    cur[i] = val;
    if (i == n - 1) rowptr[n] = val + deg[n - 1];
}
__global__ void fill_csr_kernel(const int* __restrict__ src, const int* __restrict__ dst,
                                int E, int* __restrict__ cur, int* __restrict__ eidx) {
    for (int e = blockIdx.x * blockDim.x + threadIdx.x; e < E; e += gridDim.x * blockDim.x) {
        int d = dst[e];
        int p = atomicAdd(&cur[d], 1);
        eidx[p] = src[e];
    }
}

// ---------------- prep kernels ----------------
__global__ void prep_weights_kernel(const float* W1, const float* W2, const float* W3,
                                    const float* P1, const float* P2,
                                    __nv_bfloat16* hi, __nv_bfloat16* lo) {
    int idx = blockIdx.x * blockDim.x + threadIdx.x;
    if (idx >= 5 * 16384) return;
    int w = idx >> 14;
    int t = idx & 16383;
    int n = t >> 7;
    int k = t & 127;
    const float* Ws = (w == 0) ? W1 : (w == 1) ? W2 : (w == 2) ? W3 : (w == 3) ? P1 : P2;
    float v = Ws[(k << 7) | n];
    if (w < 3) {
        __half h = __float2half_rn(v);
        float rem = v - __half2float(h);
        ((__half*)hi)[idx] = h;
        ((__half*)lo)[idx] = __float2half_rn(rem);
    } else {
        __nv_bfloat16 h = __float2bfloat16(v);
        float rem = v - __bfloat162float(h);
        hi[idx] = h;
        lo[idx] = __float2bfloat16(rem);
    }
}
__global__ void xhalf_kernel(const float* __restrict__ x, __half* __restrict__ Ah, int N) {
    int n4 = N * 32;
    for (int idx = blockIdx.x * blockDim.x + threadIdx.x; idx < n4; idx += gridDim.x * blockDim.x) {
        float4 v = ((const float4*)x)[idx];
        __half2 h01 = __floats2half2_rn(v.x, v.y);
        __half2 h23 = __floats2half2_rn(v.z, v.w);
        uint2 p;
        p.x = *(uint32_t*)&h01; p.y = *(uint32_t*)&h23;
        *(uint2*)(Ah + (size_t)idx * 4) = p;
    }
}

// ================= fp16 2-pass GEMM (trunk): Ch = A @ (Wh + Wl), fp16 out =================
#define ASTRIDE 136
#define TM 64
#define ABUF (TM * ASTRIDE)
#define WBUF (128 * ASTRIDE)
#define H_SA 0
#define H_SWH ABUF
#define H_SWL (ABUF + WBUF)
#define H_ELEMS (ABUF + 2 * WBUF)
#define H_SMEM_BYTES (H_ELEMS * 2 + 64)

__global__ void __launch_bounds__(256, 2)
gemm_f16_kernel(const __half* __restrict__ A,
                const __half* __restrict__ Wt_hi, const __half* __restrict__ Wt_lo,
                __half* __restrict__ Ch, int M, int numTiles) {
    extern __shared__ __half smh[];
    uint32_t sbase = smem_u32(smh);
    int tid = threadIdx.x, wid = tid >> 5, lane = tid & 31;

    {
        const uint4* wh = (const uint4*)Wt_hi;
        const uint4* wl = (const uint4*)Wt_lo;
        for (int i = tid; i < 2048; i += 256) {
            int r = i >> 4, c = i & 15;
            *(uint4*)(smh + H_SWH + r * ASTRIDE + c * 8) = wh[i];
            *(uint4*)(smh + H_SWL + r * ASTRIDE + c * 8) = wl[i];
        }
    }

    int mwid = wid >> 2;
    int nwid = wid & 3;
    int mrow0 = mwid << 5;
    int ncol0 = nwid << 5;

    uint32_t aRel = (uint32_t)(mrow0 + (lane & 15)) * (ASTRIDE * 2)
                  + (uint32_t)(((lane >> 4) << 3) * 2);
    uint32_t a0 = sbase + (H_SA * 2) + aRel;
    uint32_t a1 = a0 + 16 * (ASTRIDE * 2);

    uint32_t bN = (uint32_t)(ncol0 + ((lane >> 4) << 3) + (lane & 7));
    uint32_t bKB = (uint32_t)((((lane >> 3) & 1) << 3) * 2);
    uint32_t bHiBase = sbase + (H_SWH * 2) + bN * (ASTRIDE * 2) + bKB;
    uint32_t bLoBase = bHiBase + WBUF * 2;

    for (int t = blockIdx.x; t < numTiles; t += gridDim.x) {
        int row0 = t * TM;
        #pragma unroll
        for (int it = 0; it < 4; it++) {
            int idx = it * 256 + tid;
            int r = idx >> 4, c = idx & 15;
            size_t goff = (size_t)(row0 + r) * D + c * 8;
            uint32_t soff = (r * ASTRIDE + c * 8) * 2;
            cp_async16(sbase + (H_SA * 2) + soff, A + goff);
        }
        CP_COMMIT();
        cp_wait<0>();
        __syncthreads();

        float acc[2][4][4];
        #pragma unroll
        for (int mt = 0; mt < 2; mt++)
            #pragma unroll
            for (int nt = 0; nt < 4; nt++)
                #pragma unroll
                for (int q = 0; q < 4; q++) acc[mt][nt][q] = 0.0f;

        #pragma unroll
        for (int ks = 0; ks < 8; ks++) {
            uint32_t koffB = (uint32_t)(ks * 32);
            uint32_t af[2][4];
            ldsm4(af[0], a0 + koffB);
            ldsm4(af[1], a1 + koffB);
            uint32_t bh[4][2], bl[4][2];
            #pragma unroll
            for (int np = 0; np < 2; np++) {
                uint32_t r4[4];
                ldsm4(r4, bHiBase + (uint32_t)(np * 16 * ASTRIDE * 2) + koffB);
                bh[2 * np][0] = r4[0]; bh[2 * np][1] = r4[1];
                bh[2 * np + 1][0] = r4[2]; bh[2 * np + 1][1] = r4[3];
                ldsm4(r4, bLoBase + (uint32_t)(np * 16 * ASTRIDE * 2) + koffB);
                bl[2 * np][0] = r4[0]; bl[2 * np][1] = r4[1];
                bl[2 * np + 1][0] = r4[2]; bl[2 * np + 1][1] = r4[3];
            }
            #pragma unroll
            for (int mt = 0; mt < 2; mt++)
                #pragma unroll
                for (int nt = 0; nt < 4; nt++) {
                    mma_f16(acc[mt][nt], af[mt], bh[nt]);
                    mma_f16(acc[mt][nt], af[mt], bl[nt]);
                }
        }

        int cbase = ncol0 + ((lane & 3) << 1);
        int rbase = row0 + mrow0 + (lane >> 2);
        #pragma unroll
        for (int mt = 0; mt < 2; mt++) {
            #pragma unroll
            for (int half = 0; half < 2; half++) {
                int gr = rbase + mt * 16 + half * 8;
                if (gr >= M) continue;
                __half* cp = Ch + (size_t)gr * D;
                #pragma unroll
                for (int nt = 0; nt < 4; nt++) {
                    int col = cbase + nt * 8;
                    __half2 hp = __floats2half2_rn(acc[mt][nt][2 * half],
                                                   acc[mt][nt][2 * half + 1]);
                    *(uint32_t*)(cp + col) = *(uint32_t*)&hp;
                }
            }
        }
        __syncthreads();
    }
}

// ================= bf16 3-pass GEMM (link predictor) =================
#define B_SAHI 0
#define B_SALO ABUF
#define B_SWH (2 * ABUF)
#define B_SWL (2 * ABUF + WBUF)
#define B_ELEMS (2 * ABUF + 2 * WBUF)
#define B_SMEM_BYTES (B_ELEMS * 2 + (512 + 256 + 8) * 4)

__global__ void __launch_bounds__(256, 2)
gemm_bf16_kernel(const __nv_bfloat16* __restrict__ Ahi, const __nv_bfloat16* __restrict__ Alo,
                 const float* __restrict__ embf, const int* __restrict__ tedg,
                 const __nv_bfloat16* __restrict__ Wt_hi, const __nv_bfloat16* __restrict__ Wt_lo,
                 const float* __restrict__ bias,
                 __nv_bfloat16* __restrict__ OutHi, __nv_bfloat16* __restrict__ OutLo,
                 const float* __restrict__ P3, const float* __restrict__ pb3,
                 float* __restrict__ outF,
                 int M, int numTiles, int stagemode, int epimode) {
    extern __shared__ __nv_bfloat16 sm[];
    uint32_t sbase = smem_u32(sm);
    float* fpart = (float*)(sm + B_ELEMS);
    float* fP3 = fpart + 512;
    float* fpb3 = fP3 + 256;
    int tid = threadIdx.x, wid = tid >> 5, lane = tid & 31;

    {
        const uint4* wh = (const uint4*)Wt_hi;
        const uint4* wl = (const uint4*)Wt_lo;
        for (int i = tid; i < 2048; i += 256) {
            int r = i >> 4, c = i & 15;
            *(uint4*)(sm + B_SWH + r * ASTRIDE + c * 8) = wh[i];
            *(uint4*)(sm + B_SWL + r * ASTRIDE + c * 8) = wl[i];
        }
        if (epimode == 2) {
            fP3[tid] = P3[tid];
            if (tid < 2) fpb3[tid] = pb3[tid];
        }
    }

    int mwid = wid >> 2;
    int nwid = wid & 3;
    int mrow0 = mwid << 5;
    int ncol0 = nwid << 5;

    uint32_t aRel = (uint32_t)(mrow0 + (lane & 15)) * (ASTRIDE * 2)
                  + (uint32_t)(((lane >> 4) << 3) * 2);
    uint32_t aHi0 = sbase + (B_SAHI * 2) + aRel;
    uint32_t aHi1 = aHi0 + 16 * (ASTRIDE * 2);
    uint32_t aLo0 = aHi0 + ABUF * 2;
    uint32_t aLo1 = aHi1 + ABUF * 2;

    uint32_t bN = (uint32_t)(ncol0 + ((lane >> 4) << 3) + (lane & 7));
    uint32_t bKB = (uint32_t)((((lane >> 3) & 1) << 3) * 2);
    uint32_t bHiBase = sbase + (B_SWH * 2) + bN * (ASTRIDE * 2) + bKB;
    uint32_t bLoBase = bHiBase + WBUF * 2;

    for (int t = blockIdx.x; t < numTiles; t += gridDim.x) {
        int row0 = t * TM;

        if (stagemode == 0) {
            #pragma unroll
            for (int it = 0; it < 4; it++) {
                int idx = it * 256 + tid;
                int r = idx >> 4, c = idx & 15;
                size_t goff = (size_t)(row0 + r) * D + c * 8;
                uint32_t soff = (r * ASTRIDE + c * 8) * 2;
                cp_async16(sbase + (B_SAHI * 2) + soff, Ahi + goff);
                cp_async16(sbase + (B_SALO * 2) + soff, Alo + goff);
            }
            CP_COMMIT();
            cp_wait<0>();
        } else {
            #pragma unroll
            for (int it = 0; it < 8; it++) {
                int idx = it * 256 + tid;
                int r = idx >> 5;
                int c4 = idx & 31;
                int grow = row0 + r;
                float4 v;
                if (grow < M) {
                    int s = tedg[2 * grow];
                    int d = tedg[2 * grow + 1];
                    float4 a = *(const float4*)(embf + (size_t)s * D + c4 * 4);
                    float4 b = *(const float4*)(embf + (size_t)d * D + c4 * 4);
                    v = make_float4(a.x * b.x, a.y * b.y, a.z * b.z, a.w * b.w);
                } else {
                    v = make_float4(0.f, 0.f, 0.f, 0.f);
                }
                uint2 hp, lp;
                split2b(v.x, v.y, hp.x, lp.x);
                split2b(v.z, v.w, hp.y, lp.y);
                *(uint2*)(sm + B_SAHI + r * ASTRIDE + c4 * 4) = hp;
                *(uint2*)(sm + B_SALO + r * ASTRIDE + c4 * 4) = lp;
            }
        }
        __syncthreads();

        float acc[2][4][4];
        #pragma unroll
        for (int mt = 0; mt < 2; mt++)
            #pragma unroll
            for (int nt = 0; nt < 4; nt++)
                #pragma unroll
                for (int q = 0; q < 4; q++) acc[mt][nt][q] = 0.0f;

        #pragma unroll
        for (int ks = 0; ks < 8; ks++) {
            uint32_t koffB = (uint32_t)(ks * 32);
            uint32_t ah[2][4], al[2][4];
            ldsm4(ah[0], aHi0 + koffB);
            ldsm4(ah[1], aHi1 + koffB);
            ldsm4(al[0], aLo0 + koffB);
            ldsm4(al[1], aLo1 + koffB);
            uint32_t bh[4][2], bl[4][2];
            #pragma unroll
            for (int np = 0; np < 2; np++) {
                uint32_t r4[4];
                ldsm4(r4, bHiBase + (uint32_t)(np * 16 * ASTRIDE * 2) + koffB);
                bh[2 * np][0] = r4[0]; bh[2 * np][1] = r4[1];
                bh[2 * np + 1][0] = r4[2]; bh[2 * np + 1][1] = r4[3];
                ldsm4(r4, bLoBase + (uint32_t)(np * 16 * ASTRIDE * 2) + koffB);
                bl[2 * np][0] = r4[0]; bl[2 * np][1] = r4[1];
                bl[2 * np + 1][0] = r4[2]; bl[2 * np + 1][1] = r4[3];
            }
            #pragma unroll
            for (int mt = 0; mt < 2; mt++)
                #pragma unroll
                for (int nt = 0; nt < 4; nt++) {
                    mma_bf16(acc[mt][nt], ah[mt], bh[nt]);
                    mma_bf16(acc[mt][nt], ah[mt], bl[nt]);
                    mma_bf16(acc[mt][nt], al[mt], bh[nt]);
                }
        }

        int cbase = ncol0 + ((lane & 3) << 1);

        if (epimode == 2) {
            float q0a[4], q1a[4];
            #pragma unroll
            for (int mt = 0; mt < 2; mt++) {
                #pragma unroll
                for (int half = 0; half < 2; half++) {
                    float q0 = 0.f, q1 = 0.f;
                    #pragma unroll
                    for (int nt = 0; nt < 4; nt++) {
                        int col = cbase + nt * 8;
                        float z0 = fmaxf(acc[mt][nt][2 * half] + bias[col], 0.f);
                        float z1 = fmaxf(acc[mt][nt][2 * half + 1] + bias[col + 1], 0.f);
                        q0 += z0 * fP3[2 * col] + z1 * fP3[2 * (col + 1)];
                        q1 += z0 * fP3[2 * col + 1] + z1 * fP3[2 * (col + 1) + 1];
                    }
                    q0 += __shfl_xor_sync(0xFFFFFFFFu, q0, 1);
                    q0 += __shfl_xor_sync(0xFFFFFFFFu, q0, 2);
                    q1 += __shfl_xor_sync(0xFFFFFFFFu, q1, 1);
                    q1 += __shfl_xor_sync(0xFFFFFFFFu, q1, 2);
                    q0a[mt * 2 + half] = q0;
                    q1a[mt * 2 + half] = q1;
                    if (nwid != 0 && (lane & 3) == 0) {
                        int rl = mrow0 + mt * 16 + half * 8 + (lane >> 2);
                        fpart[rl * 8 + nwid * 2]     = q0;
                        fpart[rl * 8 + nwid * 2 + 1] = q1;
                    }
                }
            }
            __syncthreads();
            if (nwid == 0 && (lane & 3) == 0) {
                #pragma unroll
                for (int mt = 0; mt < 2; mt++) {
                    #pragma unroll
                    for (int half = 0; half < 2; half++) {
                        int rl = mrow0 + mt * 16 + half * 8 + (lane >> 2);
                        int gr = row0 + rl;
                        if (gr < M) {
                            float z0 = q0a[mt * 2 + half] + fpb3[0];
                            float z1 = q1a[mt * 2 + half] + fpb3[1];
                            #pragma unroll
                            for (int nw = 1; nw < 4; nw++) {
                                z0 += fpart[rl * 8 + nw * 2];
                                z1 += fpart[rl * 8 + nw * 2 + 1];
                            }
                            float nrm = fmaxf(sqrtf(z0 * z0 + z1 * z1), 1e-12f);
                            z0 /= nrm; z1 /= nrm;
                            float mm = fmaxf(z0, z1);
                            float lse = mm + logf(expf(z0 - mm) + expf(z1 - mm));
                            outF[2 * gr]     = z0 - lse;
                            outF[2 * gr + 1] = z1 - lse;
                        }
                    }
                }
            }
        } else {
            int rbase = row0 + mrow0 + (lane >> 2);
            #pragma unroll
            for (int mt = 0; mt < 2; mt++) {
                #pragma unroll
                for (int half = 0; half < 2; half++) {
                    int gr = rbase + mt * 16 + half * 8;
                    if (gr >= M) continue;
                    #pragma unroll
                    for (int nt = 0; nt < 4; nt++) {
                        int col = cbase + nt * 8;
                        float o0 = fmaxf(acc[mt][nt][2 * half] + bias[col], 0.f);
                        float o1 = fmaxf(acc[mt][nt][2 * half + 1] + bias[col + 1], 0.f);
                        uint32_t hp, lp;
                        split2b(o0, o1, hp, lp);
                        *(uint32_t*)(OutHi + (size_t)gr * D + col) = hp;
                        *(uint32_t*)(OutLo + (size_t)gr * D + col) = lp;
                    }
                }
            }
        }
        __syncthreads();
    }
}

// ---------------- aggregation: warp-per-dst, fp16 gather; out fp16 or fp32 ----------------
__global__ void agg_kernel(const __half* __restrict__ H, const int* __restrict__ rowptr,
                           const int* __restrict__ eidx, const float* __restrict__ bias,
                           __half* __restrict__ OutH, float* __restrict__ OutF,
                           int relu, int outmode, int N) {
    int gw = (blockIdx.x * blockDim.x + threadIdx.x) >> 5;
    int lane = threadIdx.x & 31;
    if (gw >= N) return;
    int beg = rowptr[gw], end = rowptr[gw + 1];
    float4 acc = make_float4(0.f, 0.f, 0.f, 0.f);
    for (int j0 = beg; j0 < end; j0 += 32) {
        int cnt = min(32, end - j0);
        int e = (lane < cnt) ? eidx[j0 + lane] : 0;
        for (int t = 0; t < cnt; t++) {
            int s = __shfl_sync(0xFFFFFFFFu, e, t);
            uint2 raw = *(const uint2*)(H + (size_t)s * D + (lane << 2));
            __half2 h01 = *(__half2*)&raw.x;
            __half2 h23 = *(__half2*)&raw.y;
            float2 f01 = __half22float2(h01);
            float2 f23 = __half22float2(h23);
            acc.x += f01.x; acc.y += f01.y; acc.z += f23.x; acc.w += f23.y;
        }
    }
    float4 bv = *(const float4*)(bias + (lane << 2));
    acc.x += bv.x; acc.y += bv.y; acc.z += bv.z; acc.w += bv.w;
    if (relu) {
        acc.x = fmaxf(acc.x, 0.f); acc.y = fmaxf(acc.y, 0.f);
        acc.z = fmaxf(acc.z, 0.f); acc.w = fmaxf(acc.w, 0.f);
    }
    if (outmode == 0) {
        __half2 h01 = __floats2half2_rn(acc.x, acc.y);
        __half2 h23 = __floats2half2_rn(acc.z, acc.w);
        uint2 p;
        p.x = *(uint32_t*)&h01; p.y = *(uint32_t*)&h23;
        *(uint2*)(OutH + (size_t)gw * D + (lane << 2)) = p;
    } else {
        *(float4*)(OutF + (size_t)gw * D + (lane << 2)) = acc;
    }
}

// ---------------- launch ----------------
extern "C" void kernel_launch(void* const* d_in, const int* in_sizes, int n_in,
                              void* d_out, int out_size) {
    const float* x    = (const float*)d_in[0];
    const int*   adj  = (const int*)d_in[1];
    const int*   tedg = (const int*)d_in[2];
    const float* W1 = (const float*)d_in[3];  const float* b1  = (const float*)d_in[4];
    const float* W2 = (const float*)d_in[5];  const float* b2  = (const float*)d_in[6];
    const float* W3 = (const float*)d_in[7];  const float* b3  = (const float*)d_in[8];
    const float* P1 = (const float*)d_in[9];  const float* pb1 = (const float*)d_in[10];
    const float* P2 = (const float*)d_in[11]; const float* pb2 = (const float*)d_in[12];
    const float* P3 = (const float*)d_in[13]; const float* pb3 = (const float*)d_in[14];
    float* out = (float*)d_out;

    int N  = in_sizes[0] / D;
    int E  = in_sizes[1] / 2;
    int NE = in_sizes[2] / 2;

    cudaFuncSetAttribute((const void*)gemm_f16_kernel,
                         cudaFuncAttributeMaxDynamicSharedMemorySize, H_SMEM_BYTES);
    cudaFuncSetAttribute((const void*)gemm_bf16_kernel,
                         cudaFuncAttributeMaxDynamicSharedMemorySize, B_SMEM_BYTES);

    __nv_bfloat16 *Ahi, *Alo, *Whi, *Wlo;
    __half* Hh;
    float* emb;
    int *deg, *rowptr, *cur, *eidx, *bsum;
    cudaGetSymbolAddress((void**)&Ahi, g_Ahi);
    cudaGetSymbolAddress((void**)&Alo, g_Alo);
    cudaGetSymbolAddress((void**)&Hh,  g_Hh);
    cudaGetSymbolAddress((void**)&emb, g_emb);
    cudaGetSymbolAddress((void**)&deg,    g_deg);
    cudaGetSymbolAddress((void**)&rowptr, g_rowptr);
    cudaGetSymbolAddress((void**)&cur,    g_cur);
    cudaGetSymbolAddress((void**)&eidx,   g_eidx);
    cudaGetSymbolAddress((void**)&bsum,   g_bsum);
    cudaGetSymbolAddress((void**)&Whi,  g_Whi);
    cudaGetSymbolAddress((void**)&Wlo,  g_Wlo);

    __half* Ah16 = (__half*)Ahi;                   // trunk A (fp16 single buffer)
    const __half* Wh16 = (const __half*)Whi;
    const __half* Wl16 = (const __half*)Wlo;

    const int* src = adj;
    const int* dst = adj + E;

    int nScanBlk = (N + 1023) / 1024;
    int tilesN  = (N + TM - 1) / TM;
    int tilesNE = (NE + TM - 1) / TM;
    int gN  = tilesN  < 296 ? tilesN  : 296;
    int gNE = tilesNE < 296 ? tilesNE : 296;
    int aggBlk = (N * 32 + 255) / 256;

    // ---- prep + L1 GEMM early, CSR chain after ----
    prep_weights_kernel<<<(5 * 16384 + 255) / 256, 256>>>(W1, W2, W3, P1, P2, Whi, Wlo);
    xhalf_kernel<<<2048, 256>>>(x, Ah16, N);
    zero_int_kernel<<<(N + 255) / 256, 256>>>(deg, N);
    gemm_f16_kernel<<<gN, 256, H_SMEM_BYTES>>>(Ah16, Wh16, Wl16, Hh, N, tilesN);
    hist_kernel<<<(E + 255) / 256, 256>>>(dst, E, deg);
    scan1_kernel<<<nScanBlk, 1024>>>(deg, rowptr, bsum, N);
    scan2_kernel<<<1, 32>>>(bsum, nScanBlk);
    scan3_kernel<<<nScanBlk, 1024>>>(deg, rowptr, cur, bsum, N);
    fill_csr_kernel<<<(E + 255) / 256, 256>>>(src, dst, E, cur, eidx);

    // ---- trunk ----
    agg_kernel<<<aggBlk, 256>>>(Hh, rowptr, eidx, b1, Ah16, nullptr, 1, 0, N);
    gemm_f16_kernel<<<gN, 256, H_SMEM_BYTES>>>(Ah16, Wh16 + 16384, Wl16 + 16384, Hh, N, tilesN);
    agg_kernel<<<aggBlk, 256>>>(Hh, rowptr, eidx, b2, Ah16, nullptr, 1, 0, N);
    gemm_f16_kernel<<<gN, 256, H_SMEM_BYTES>>>(Ah16, Wh16 + 2 * 16384, Wl16 + 2 * 16384, Hh, N, tilesN);
    agg_kernel<<<aggBlk, 256>>>(Hh, rowptr, eidx, b3, nullptr, emb, 0, 1, N);

    // ---- link predictor (bf16 3-pass) ----
    gemm_bf16_kernel<<<gNE, 256, B_SMEM_BYTES>>>(nullptr, nullptr, emb, tedg,
        Whi + 3 * 16384, Wlo + 3 * 16384, pb1, Ahi, Alo, nullptr, nullptr, nullptr,
        NE, tilesNE, 1, 1);
    gemm_bf16_kernel<<<gNE, 256, B_SMEM_BYTES>>>(Ahi, Alo, nullptr, nullptr,
        Whi + 4 * 16384, Wlo + 4 * 16384, pb2, nullptr, nullptr, P3, pb3, out,
        NE, tilesNE, 0, 2);
}